// round 8
// baseline (speedup 1.0000x reference)
#include <cuda_runtime.h>

#define HID   1024
#define HEADS 16
#define HD    64
#define SEQ   2048
#define BATCH 4
#define M_TOT (BATCH * SEQ)               // 8192
#define BHSD  (BATCH * HEADS * SEQ * HD)  // 8388608 per matrix

// Scratch (static device arrays — no cudaMalloc anywhere)
__device__ float g_Weff[3 * HID * HID];   // folded LoRA weights (12 MB)
__device__ float g_qkv[3 * BHSD];         // Q,K,V in [b,h,s,d] layout (96 MB)

struct Ptrs3 { const float* p[3]; };

// ---------------------------------------------------------------------------
// 1) Fold LoRA into the dense weight: Weff = W + (1/RANK) * B @ A
//    W: [1024,1024] row-major, B: [1024,16], A: [16,1024]. blockIdx.y = mat.
// ---------------------------------------------------------------------------
__global__ __launch_bounds__(256) void fold_lora_kernel(Ptrs3 W, Ptrs3 A, Ptrs3 Bm) {
    const int mat = blockIdx.y;
    const float* __restrict__ Wp = W.p[mat];
    const float* __restrict__ Ap = A.p[mat];
    const float* __restrict__ Bp = Bm.p[mat];
    int idx = blockIdx.x * 256 + threadIdx.x;      // 0 .. 1024*1024-1
    int i = idx >> 10;                             // out row
    int j = idx & 1023;                            // in col
    float acc = 0.f;
#pragma unroll
    for (int r = 0; r < 16; r++)
        acc += Bp[(i << 4) + r] * Ap[(r << 10) + j];
    g_Weff[mat * HID * HID + idx] = Wp[idx] + acc * (1.0f / 16.0f);
}

// ---------------------------------------------------------------------------
// 2) QKV projection GEMM: Y[m][n] = sum_k X[m][k] * Weff[n][k] + bias[n]
//    128x128 tile, BK=8, 256 threads, 8x8 per-thread micro-tile.
//    blockIdx.z = mat (q/k/v). Epilogue writes head-transposed layout
//    g_qkv[mat][b][h][s][d].
// ---------------------------------------------------------------------------
__global__ __launch_bounds__(256) void qkv_gemm_kernel(const float* __restrict__ X,
                                                       Ptrs3 bias) {
    __shared__ float As[8][128];
    __shared__ float Bs[8][128];
    const int mat = blockIdx.z;
    const float* __restrict__ Wf = g_Weff + mat * HID * HID;
    const float* __restrict__ bp = bias.p[mat];

    const int tid = threadIdx.x;
    const int tx = tid & 15, ty = tid >> 4;
    const int m0 = blockIdx.y << 7;
    const int n0 = blockIdx.x << 7;
    const int lr = tid >> 1;           // 0..127 : tile row this thread loads
    const int lc = (tid & 1) << 2;     // 0 or 4 : k offset (float4)

    float acc[8][8];
#pragma unroll
    for (int i = 0; i < 8; i++)
#pragma unroll
        for (int j = 0; j < 8; j++) acc[i][j] = 0.f;

    for (int k0 = 0; k0 < HID; k0 += 8) {
        float4 xa = *(const float4*)(X  + (m0 + lr) * HID + k0 + lc);
        float4 wb = *(const float4*)(Wf + (n0 + lr) * HID + k0 + lc);
        As[lc + 0][lr] = xa.x; As[lc + 1][lr] = xa.y;
        As[lc + 2][lr] = xa.z; As[lc + 3][lr] = xa.w;
        Bs[lc + 0][lr] = wb.x; Bs[lc + 1][lr] = wb.y;
        Bs[lc + 2][lr] = wb.z; Bs[lc + 3][lr] = wb.w;
        __syncthreads();
#pragma unroll
        for (int k = 0; k < 8; k++) {
            float a[8], b[8];
            *(float4*)(a)     = *(const float4*)(&As[k][(ty << 3)]);
            *(float4*)(a + 4) = *(const float4*)(&As[k][(ty << 3) + 4]);
            *(float4*)(b)     = *(const float4*)(&Bs[k][(tx << 3)]);
            *(float4*)(b + 4) = *(const float4*)(&Bs[k][(tx << 3) + 4]);
#pragma unroll
            for (int i = 0; i < 8; i++)
#pragma unroll
                for (int j = 0; j < 8; j++)
                    acc[i][j] = fmaf(a[i], b[j], acc[i][j]);
        }
        __syncthreads();
    }

    float* __restrict__ outp = g_qkv + mat * BHSD;
#pragma unroll
    for (int i = 0; i < 8; i++) {
        int m = m0 + (ty << 3) + i;
        int bb = m >> 11;              // batch
        int s  = m & 2047;             // seq pos
#pragma unroll
        for (int jj = 0; jj < 8; jj += 4) {
            int n  = n0 + (tx << 3) + jj;
            int hh = n >> 6;           // head
            int dd = n & 63;           // dim within head (8-aligned -> same head)
            float4 v;
            v.x = acc[i][jj + 0] + bp[n + 0];
            v.y = acc[i][jj + 1] + bp[n + 1];
            v.z = acc[i][jj + 2] + bp[n + 2];
            v.w = acc[i][jj + 3] + bp[n + 3];
            *(float4*)(outp + (((bb << 4) + hh) * SEQ + s) * HD + dd) = v;
        }
    }
}

// ---------------------------------------------------------------------------
// 3) Flash attention, fp32. One CTA = (bh, 64-query block). 256 threads.
//    Q and K stored d-major (transposed, stride 68) for conflict-free
//    outer products; KPt smem is reused for transposed P in the PV gemm.
// ---------------------------------------------------------------------------
#define QK_STRIDE 68
#define FLASH_SMEM_FLOATS (64 * QK_STRIDE * 2 + 64 * 64 + 64)

__global__ __launch_bounds__(256) void flash_attn_kernel(const float* __restrict__ mask,
                                                         float* __restrict__ out) {
    extern __shared__ float sm[];
    float* Qt  = sm;                          // [64 d][68] transposed Q (pre-scaled)
    float* KPt = sm + 64 * QK_STRIDE;         // [64 d][68] transposed K, reused as Pt
    float* Vs  = sm + 2 * 64 * QK_STRIDE;     // [64 s][64 d]
    float* msk = Vs + 64 * 64;                // [64]

    const int tid = threadIdx.x;
    const int tx = tid & 15, ty = tid >> 4;
    const int bh = blockIdx.y;
    const int b = bh >> 4, h = bh & 15;
    const int q0 = blockIdx.x << 6;

    const float* __restrict__ qp = g_qkv + 0 * BHSD + bh * (SEQ * HD);
    const float* __restrict__ kp = g_qkv + 1 * BHSD + bh * (SEQ * HD);
    const float* __restrict__ vp = g_qkv + 2 * BHSD + bh * (SEQ * HD);

    // Load Q tile transposed, pre-scaled by 1/sqrt(64) = 0.125
    {
        const int r  = tid >> 4;
        const int dq = (tid & 15) << 2;
#pragma unroll
        for (int it = 0; it < 4; it++) {
            int rr = r + (it << 4);
            float4 v = *(const float4*)(qp + (q0 + rr) * HD + dq);
            Qt[(dq + 0) * QK_STRIDE + rr] = v.x * 0.125f;
            Qt[(dq + 1) * QK_STRIDE + rr] = v.y * 0.125f;
            Qt[(dq + 2) * QK_STRIDE + rr] = v.z * 0.125f;
            Qt[(dq + 3) * QK_STRIDE + rr] = v.w * 0.125f;
        }
    }

    float Oacc[4][4];
    float m_i[4], l_i[4];
#pragma unroll
    for (int i = 0; i < 4; i++) {
        m_i[i] = -1e30f; l_i[i] = 0.f;
#pragma unroll
        for (int j = 0; j < 4; j++) Oacc[i][j] = 0.f;
    }

    for (int kt = 0; kt < SEQ / 64; kt++) {
        __syncthreads();   // previous iteration readers of KPt/Vs are done
        {
            const int r  = tid >> 4;
            const int dq = (tid & 15) << 2;
#pragma unroll
            for (int it = 0; it < 4; it++) {
                int rr = r + (it << 4);
                float4 kv = *(const float4*)(kp + (kt * 64 + rr) * HD + dq);
                KPt[(dq + 0) * QK_STRIDE + rr] = kv.x;
                KPt[(dq + 1) * QK_STRIDE + rr] = kv.y;
                KPt[(dq + 2) * QK_STRIDE + rr] = kv.z;
                KPt[(dq + 3) * QK_STRIDE + rr] = kv.w;
                float4 vv = *(const float4*)(vp + (kt * 64 + rr) * HD + dq);
                *(float4*)(Vs + rr * 64 + dq) = vv;
            }
            if (tid < 64) msk[tid] = mask[b * SEQ + kt * 64 + tid];
        }
        __syncthreads();

        // S = (Q/sqrt(d)) @ K^T   (4x4 per thread, outer product over d)
        float S[4][4];
#pragma unroll
        for (int i = 0; i < 4; i++)
#pragma unroll
            for (int j = 0; j < 4; j++) S[i][j] = 0.f;

#pragma unroll 8
        for (int d = 0; d < 64; d++) {
            float4 qv = *(const float4*)(Qt  + d * QK_STRIDE + (ty << 2));
            float4 kv = *(const float4*)(KPt + d * QK_STRIDE + (tx << 2));
            float qa[4] = {qv.x, qv.y, qv.z, qv.w};
            float kb[4] = {kv.x, kv.y, kv.z, kv.w};
#pragma unroll
            for (int i = 0; i < 4; i++)
#pragma unroll
                for (int j = 0; j < 4; j++)
                    S[i][j] = fmaf(qa[i], kb[j], S[i][j]);
        }

        // online softmax (rows reduced across 16-lane groups)
        float p[4][4];
#pragma unroll
        for (int i = 0; i < 4; i++) {
            float mx = -1e30f;
#pragma unroll
            for (int j = 0; j < 4; j++) {
                S[i][j] += msk[(tx << 2) + j];
                mx = fmaxf(mx, S[i][j]);
            }
#pragma unroll
            for (int o = 1; o < 16; o <<= 1)
                mx = fmaxf(mx, __shfl_xor_sync(0xffffffffu, mx, o));
            float mnew = fmaxf(m_i[i], mx);
            float scl = __expf(m_i[i] - mnew);
            float rs = 0.f;
#pragma unroll
            for (int j = 0; j < 4; j++) {
                p[i][j] = __expf(S[i][j] - mnew);
                rs += p[i][j];
            }
#pragma unroll
            for (int o = 1; o < 16; o <<= 1)
                rs += __shfl_xor_sync(0xffffffffu, rs, o);
            l_i[i] = l_i[i] * scl + rs;
            m_i[i] = mnew;
#pragma unroll
            for (int j = 0; j < 4; j++) Oacc[i][j] *= scl;
        }

        __syncthreads();   // all threads done reading KPt as K
        // store P transposed into KPt: Pt[kk][q]
#pragma unroll
        for (int j = 0; j < 4; j++)
#pragma unroll
            for (int i = 0; i < 4; i++)
                KPt[((tx << 2) + j) * QK_STRIDE + (ty << 2) + i] = p[i][j];
        __syncthreads();

        // O += P @ V  (outer product over kk)
#pragma unroll 8
        for (int kk = 0; kk < 64; kk++) {
            float4 pv = *(const float4*)(KPt + kk * QK_STRIDE + (ty << 2));
            float4 vv = *(const float4*)(Vs  + kk * 64        + (tx << 2));
            float pa[4] = {pv.x, pv.y, pv.z, pv.w};
            float vb[4] = {vv.x, vv.y, vv.z, vv.w};
#pragma unroll
            for (int i = 0; i < 4; i++)
#pragma unroll
                for (int j = 0; j < 4; j++)
                    Oacc[i][j] = fmaf(pa[i], vb[j], Oacc[i][j]);
        }
    }

    // epilogue: normalize, write out[b][s][h*64+d]
#pragma unroll
    for (int i = 0; i < 4; i++) {
        float inv = 1.0f / l_i[i];
        int s = q0 + (ty << 2) + i;
        float4 v;
        v.x = Oacc[i][0] * inv;
        v.y = Oacc[i][1] * inv;
        v.z = Oacc[i][2] * inv;
        v.w = Oacc[i][3] * inv;
        *(float4*)(out + (b * SEQ + s) * HID + h * HD + (tx << 2)) = v;
    }
}

// ---------------------------------------------------------------------------
// Launch
// ---------------------------------------------------------------------------
extern "C" void kernel_launch(void* const* d_in, const int* in_sizes, int n_in,
                              void* d_out, int out_size) {
    (void)in_sizes; (void)n_in; (void)out_size;
    const float* x    = (const float*)d_in[0];
    const float* mask = (const float*)d_in[1];
    Ptrs3 W  = {{(const float*)d_in[2],  (const float*)d_in[6],  (const float*)d_in[10]}};
    Ptrs3 bi = {{(const float*)d_in[3],  (const float*)d_in[7],  (const float*)d_in[11]}};
    Ptrs3 A  = {{(const float*)d_in[4],  (const float*)d_in[8],  (const float*)d_in[12]}};
    Ptrs3 Bl = {{(const float*)d_in[5],  (const float*)d_in[9],  (const float*)d_in[13]}};
    float* out = (float*)d_out;

    fold_lora_kernel<<<dim3((HID * HID) / 256, 3), 256>>>(W, A, Bl);

    qkv_gemm_kernel<<<dim3(HID / 128, M_TOT / 128, 3), 256>>>(x, bi);

    const int flash_smem = FLASH_SMEM_FLOATS * (int)sizeof(float);  // 51456 B
    cudaFuncSetAttribute(flash_attn_kernel,
                         cudaFuncAttributeMaxDynamicSharedMemorySize, flash_smem);
    flash_attn_kernel<<<dim3(SEQ / 64, BATCH * HEADS), 256, flash_smem>>>(mask, out);
}

// round 10
// speedup vs baseline: 2.4147x; 2.4147x over previous
#include <cuda_runtime.h>
#include <cuda_bf16.h>
#include <cstdint>

#define HID   1024
#define HEADS 16
#define HD    64
#define SEQ   2048
#define BATCH 4
#define NBH   (BATCH * HEADS)     // 64
#define M_TOT (BATCH * SEQ)       // 8192

// ---- static scratch (no cudaMalloc anywhere) ----
__device__ __align__(16) __nv_bfloat16 g_Whi[3 * HID * HID];
__device__ __align__(16) __nv_bfloat16 g_Wlo[3 * HID * HID];
__device__ __align__(16) __nv_bfloat16 g_Xhi[M_TOT * HID];
__device__ __align__(16) __nv_bfloat16 g_Xlo[M_TOT * HID];
// Q/K/V split: [mat][bh][s][128]  (cols 0-63 = hi, 64-127 = lo); Q pre-scaled by 0.125
__device__ __align__(16) __nv_bfloat16 g_QKVc[3][NBH * SEQ * 128];

struct Ptrs3 { const float* p[3]; };

// ---------------------------------------------------------------------------
// PTX helpers: ldmatrix + mma.sync bf16
// ---------------------------------------------------------------------------
__device__ __forceinline__ uint32_t smaddr(const void* p) {
    return (uint32_t)__cvta_generic_to_shared(p);
}
__device__ __forceinline__ void ldsm4(uint32_t& r0, uint32_t& r1, uint32_t& r2, uint32_t& r3, uint32_t a) {
    asm volatile("ldmatrix.sync.aligned.m8n8.x4.shared.b16 {%0,%1,%2,%3}, [%4];"
                 : "=r"(r0), "=r"(r1), "=r"(r2), "=r"(r3) : "r"(a));
}
__device__ __forceinline__ void ldsm4t(uint32_t& r0, uint32_t& r1, uint32_t& r2, uint32_t& r3, uint32_t a) {
    asm volatile("ldmatrix.sync.aligned.m8n8.x4.trans.shared.b16 {%0,%1,%2,%3}, [%4];"
                 : "=r"(r0), "=r"(r1), "=r"(r2), "=r"(r3) : "r"(a));
}
__device__ __forceinline__ void mma16816(float* c, const uint32_t* a, const uint32_t* b) {
    asm volatile("mma.sync.aligned.m16n8k16.row.col.f32.bf16.bf16.f32 "
                 "{%0,%1,%2,%3},{%4,%5,%6,%7},{%8,%9},{%0,%1,%2,%3};"
                 : "+f"(c[0]), "+f"(c[1]), "+f"(c[2]), "+f"(c[3])
                 : "r"(a[0]), "r"(a[1]), "r"(a[2]), "r"(a[3]), "r"(b[0]), "r"(b[1]));
}
__device__ __forceinline__ void bfsplit(float f, __nv_bfloat16& hi, __nv_bfloat16& lo) {
    hi = __float2bfloat16_rn(f);
    lo = __float2bfloat16_rn(f - __bfloat162float(hi));
}

// ---------------------------------------------------------------------------
// 1) Fold LoRA into W and split to bf16 hi/lo.  blockIdx.y = mat.
// ---------------------------------------------------------------------------
__global__ __launch_bounds__(256) void fold_split_w(Ptrs3 W, Ptrs3 A, Ptrs3 Bm) {
    const int mat = blockIdx.y;
    const float* __restrict__ Wp = W.p[mat];
    const float* __restrict__ Ap = A.p[mat];
    const float* __restrict__ Bp = Bm.p[mat];
    int idx = blockIdx.x * 256 + threadIdx.x;
    int i = idx >> 10, j = idx & 1023;
    float acc = 0.f;
#pragma unroll
    for (int r = 0; r < 16; r++)
        acc += Bp[(i << 4) + r] * Ap[(r << 10) + j];
    float w = Wp[idx] + acc * (1.0f / 16.0f);
    __nv_bfloat16 hi, lo; bfsplit(w, hi, lo);
    g_Whi[mat * HID * HID + idx] = hi;
    g_Wlo[mat * HID * HID + idx] = lo;
}

// ---------------------------------------------------------------------------
// 2) Split X (fp32 -> bf16 hi/lo)
// ---------------------------------------------------------------------------
__global__ __launch_bounds__(256) void split_x(const float* __restrict__ X) {
    int i4 = blockIdx.x * 256 + threadIdx.x;       // over float4s
    float4 v = ((const float4*)X)[i4];
    __nv_bfloat16 h[4], l[4];
    bfsplit(v.x, h[0], l[0]); bfsplit(v.y, h[1], l[1]);
    bfsplit(v.z, h[2], l[2]); bfsplit(v.w, h[3], l[3]);
    uint2 ph, pl;
    ph.x = (uint32_t)__bfloat16_as_ushort(h[0]) | ((uint32_t)__bfloat16_as_ushort(h[1]) << 16);
    ph.y = (uint32_t)__bfloat16_as_ushort(h[2]) | ((uint32_t)__bfloat16_as_ushort(h[3]) << 16);
    pl.x = (uint32_t)__bfloat16_as_ushort(l[0]) | ((uint32_t)__bfloat16_as_ushort(l[1]) << 16);
    pl.y = (uint32_t)__bfloat16_as_ushort(l[2]) | ((uint32_t)__bfloat16_as_ushort(l[3]) << 16);
    ((uint2*)g_Xhi)[i4] = ph;
    ((uint2*)g_Xlo)[i4] = pl;
}

// ---------------------------------------------------------------------------
// 3) QKV projection GEMM (bf16x3 via mma.sync).  CTA 128m x 64n, BK=32.
//    8 warps, warp tile 32x32.  blockIdx.z = mat.  Epilogue writes split
//    bf16 Q/K/V in [bh][s][128] (Q pre-scaled 0.125).
// ---------------------------------------------------------------------------
#define ASTR 40   // smem k-stride (bf16 elems), 80B: 16B-aligned, LDSM conflict-free

__global__ __launch_bounds__(256) void qkv_gemm_mma(Ptrs3 bias) {
    __shared__ __align__(16) __nv_bfloat16 Ah[128 * ASTR];
    __shared__ __align__(16) __nv_bfloat16 Al[128 * ASTR];
    __shared__ __align__(16) __nv_bfloat16 Bh[64 * ASTR];
    __shared__ __align__(16) __nv_bfloat16 Bl[64 * ASTR];

    const int mat = blockIdx.z;
    const __nv_bfloat16* __restrict__ Whi = g_Whi + mat * HID * HID;
    const __nv_bfloat16* __restrict__ Wlo = g_Wlo + mat * HID * HID;

    const int tid = threadIdx.x, lane = tid & 31, wid = tid >> 5;
    const int m0 = blockIdx.y << 7, n0 = blockIdx.x << 6;
    const int wm = (wid >> 1) << 5;      // warp row offset (0,32,64,96)
    const int wn = (wid & 1) << 5;       // warp col offset (0,32)

    // ldmatrix per-lane offsets
    const int ar = (lane & 7) + ((lane & 8) ? 8 : 0);
    const int ac = (lane & 16) ? 8 : 0;
    const int br = (lane & 7) + ((lane >= 16) ? 8 : 0);
    const int bc = (lane & 8) ? 8 : 0;

    float acc[2][4][4];
#pragma unroll
    for (int mi = 0; mi < 2; mi++)
#pragma unroll
        for (int ni = 0; ni < 4; ni++)
#pragma unroll
            for (int q = 0; q < 4; q++) acc[mi][ni][q] = 0.f;

    for (int k0 = 0; k0 < HID; k0 += 32) {
        // load tiles
#pragma unroll
        for (int jj = 0; jj < 2; jj++) {
            int v = tid + jj * 256;                 // 0..511
            int row = v >> 2, c8 = (v & 3) << 3;
            *(uint4*)(Ah + row * ASTR + c8) = *(const uint4*)(g_Xhi + (m0 + row) * HID + k0 + c8);
            *(uint4*)(Al + row * ASTR + c8) = *(const uint4*)(g_Xlo + (m0 + row) * HID + k0 + c8);
        }
        {
            int row = tid >> 2, c8 = (tid & 3) << 3; // 256 uint4 covers 64 rows
            *(uint4*)(Bh + row * ASTR + c8) = *(const uint4*)(Whi + (n0 + row) * HID + k0 + c8);
            *(uint4*)(Bl + row * ASTR + c8) = *(const uint4*)(Wlo + (n0 + row) * HID + k0 + c8);
        }
        __syncthreads();

#pragma unroll
        for (int ks = 0; ks < 2; ks++) {
            uint32_t af[2][4], alf[2][4], bf[4][2], blf[4][2];
#pragma unroll
            for (int mi = 0; mi < 2; mi++) {
                ldsm4(af[mi][0], af[mi][1], af[mi][2], af[mi][3],
                      smaddr(Ah + (wm + mi * 16 + ar) * ASTR + ks * 16 + ac));
                ldsm4(alf[mi][0], alf[mi][1], alf[mi][2], alf[mi][3],
                      smaddr(Al + (wm + mi * 16 + ar) * ASTR + ks * 16 + ac));
            }
#pragma unroll
            for (int p = 0; p < 2; p++) {
                uint32_t r0, r1, r2, r3;
                ldsm4(r0, r1, r2, r3, smaddr(Bh + (wn + p * 16 + br) * ASTR + ks * 16 + bc));
                bf[2 * p][0] = r0; bf[2 * p][1] = r1; bf[2 * p + 1][0] = r2; bf[2 * p + 1][1] = r3;
                ldsm4(r0, r1, r2, r3, smaddr(Bl + (wn + p * 16 + br) * ASTR + ks * 16 + bc));
                blf[2 * p][0] = r0; blf[2 * p][1] = r1; blf[2 * p + 1][0] = r2; blf[2 * p + 1][1] = r3;
            }
#pragma unroll
            for (int mi = 0; mi < 2; mi++)
#pragma unroll
                for (int ni = 0; ni < 4; ni++) {
                    mma16816(acc[mi][ni], af[mi],  bf[ni]);   // hi*hi
                    mma16816(acc[mi][ni], alf[mi], bf[ni]);   // lo*hi
                    mma16816(acc[mi][ni], af[mi],  blf[ni]);  // hi*lo
                }
        }
        __syncthreads();
    }

    // epilogue: bias, optional Q scale, split, store [bh][s][128]
    const float* __restrict__ bp = bias.p[mat];
    const float qs = (mat == 0) ? 0.125f : 1.0f;
    __nv_bfloat16* __restrict__ outp = g_QKVc[mat];
#pragma unroll
    for (int mi = 0; mi < 2; mi++)
#pragma unroll
        for (int ni = 0; ni < 4; ni++) {
            int r = m0 + wm + mi * 16 + (lane >> 2);
            int c = n0 + wn + ni * 8 + 2 * (lane & 3);
            float b0 = bp[c], b1 = bp[c + 1];
            int hh = c >> 6, dd = c & 63;
#pragma unroll
            for (int h2 = 0; h2 < 2; h2++) {
                int rr = r + h2 * 8;
                int bb = rr >> 11, ss = rr & 2047;
                int bh = (bb << 4) + hh;
                float f0 = (acc[mi][ni][h2 * 2 + 0] + b0) * qs;
                float f1 = (acc[mi][ni][h2 * 2 + 1] + b1) * qs;
                __nv_bfloat16 h0, l0, h1, l1;
                bfsplit(f0, h0, l0); bfsplit(f1, h1, l1);
                uint32_t ph = (uint32_t)__bfloat16_as_ushort(h0) | ((uint32_t)__bfloat16_as_ushort(h1) << 16);
                uint32_t pl = (uint32_t)__bfloat16_as_ushort(l0) | ((uint32_t)__bfloat16_as_ushort(l1) << 16);
                size_t base = ((size_t)bh * SEQ + ss) * 128;
                *(uint32_t*)(outp + base + dd)      = ph;
                *(uint32_t*)(outp + base + 64 + dd) = pl;
            }
        }
}

// ---------------------------------------------------------------------------
// 4) Flash attention on mma.sync (bf16x3).  CTA = (64-q block, bh), 128 thr.
//    S materialized to smem for fp32 online softmax; O stays in mma regs.
// ---------------------------------------------------------------------------
#define QSTR 136    // bf16 tile stride (272B)
#define SSTR 68     // fp32 S stride
#define ATTN_SMEM (4 * 64 * QSTR * 2 + 64 * SSTR * 4 + 4 * 64 * 4)  // 88064 B

__global__ __launch_bounds__(128) void flash_mma(const float* __restrict__ mask,
                                                 float* __restrict__ out) {
    extern __shared__ __align__(16) char smbuf[];
    __nv_bfloat16* Qs = (__nv_bfloat16*)smbuf;      // [64][136] hi|lo
    __nv_bfloat16* Ks = Qs + 64 * QSTR;
    __nv_bfloat16* Vs = Ks + 64 * QSTR;
    __nv_bfloat16* Ps = Vs + 64 * QSTR;
    float* Ss     = (float*)(Ps + 64 * QSTR);       // [64][68]
    float* mrow   = Ss + 64 * SSTR;
    float* lrow   = mrow + 64;
    float* sclrow = lrow + 64;
    float* msk    = sclrow + 64;

    const int tid = threadIdx.x, lane = tid & 31, wid = tid >> 5;
    const int bh = blockIdx.y, b = bh >> 4, h = bh & 15;
    const int q0 = blockIdx.x << 6;

    const __nv_bfloat16* __restrict__ Qg = g_QKVc[0] + (size_t)bh * SEQ * 128;
    const __nv_bfloat16* __restrict__ Kg = g_QKVc[1] + (size_t)bh * SEQ * 128;
    const __nv_bfloat16* __restrict__ Vg = g_QKVc[2] + (size_t)bh * SEQ * 128;

    // load Q tile (persists)
#pragma unroll
    for (int v = tid; v < 1024; v += 128) {
        int row = v >> 4, seg = (v & 15) << 3;
        *(uint4*)(Qs + row * QSTR + seg) = *(const uint4*)(Qg + (q0 + row) * 128 + seg);
    }
    if (tid < 64) { mrow[tid] = -1e30f; lrow[tid] = 0.f; }

    float O[8][4];
#pragma unroll
    for (int ni = 0; ni < 8; ni++)
#pragma unroll
        for (int q = 0; q < 4; q++) O[ni][q] = 0.f;

    const int ar = (lane & 7) + ((lane & 8) ? 8 : 0);
    const int ac = (lane & 16) ? 8 : 0;
    const int br = (lane & 7) + ((lane >= 16) ? 8 : 0);
    const int bc = (lane & 8) ? 8 : 0;
    const int vr = lane & 15;                 // trans-ldsm row offset
    const int vc = (lane >= 16) ? 8 : 0;      // trans-ldsm col offset

    for (int kt = 0; kt < SEQ / 64; kt++) {
        __syncthreads();
        const int s0 = kt * 64;
#pragma unroll
        for (int v = tid; v < 1024; v += 128) {
            int row = v >> 4, seg = (v & 15) << 3;
            *(uint4*)(Ks + row * QSTR + seg) = *(const uint4*)(Kg + (s0 + row) * 128 + seg);
            *(uint4*)(Vs + row * QSTR + seg) = *(const uint4*)(Vg + (s0 + row) * 128 + seg);
        }
        if (tid < 64) msk[tid] = mask[b * SEQ + s0 + tid];
        __syncthreads();

        // ---- S = Qhi*Khi + Qlo*Khi + Qhi*Klo ----
        float S[8][4];
#pragma unroll
        for (int ni = 0; ni < 8; ni++)
#pragma unroll
            for (int q = 0; q < 4; q++) S[ni][q] = 0.f;

#pragma unroll
        for (int ks = 0; ks < 4; ks++) {                 // B = Khi
            uint32_t bf[8][2];
#pragma unroll
            for (int p = 0; p < 4; p++) {
                uint32_t r0, r1, r2, r3;
                ldsm4(r0, r1, r2, r3, smaddr(Ks + (p * 16 + br) * QSTR + ks * 16 + bc));
                bf[2 * p][0] = r0; bf[2 * p][1] = r1; bf[2 * p + 1][0] = r2; bf[2 * p + 1][1] = r3;
            }
            uint32_t a0[4], a1[4];
            ldsm4(a0[0], a0[1], a0[2], a0[3], smaddr(Qs + (wid * 16 + ar) * QSTR + ks * 16 + ac));
            ldsm4(a1[0], a1[1], a1[2], a1[3], smaddr(Qs + (wid * 16 + ar) * QSTR + 64 + ks * 16 + ac));
#pragma unroll
            for (int ni = 0; ni < 8; ni++) { mma16816(S[ni], a0, bf[ni]); mma16816(S[ni], a1, bf[ni]); }
        }
#pragma unroll
        for (int ks = 0; ks < 4; ks++) {                 // B = Klo, A = Qhi
            uint32_t bf[8][2];
#pragma unroll
            for (int p = 0; p < 4; p++) {
                uint32_t r0, r1, r2, r3;
                ldsm4(r0, r1, r2, r3, smaddr(Ks + (p * 16 + br) * QSTR + 64 + ks * 16 + bc));
                bf[2 * p][0] = r0; bf[2 * p][1] = r1; bf[2 * p + 1][0] = r2; bf[2 * p + 1][1] = r3;
            }
            uint32_t a0[4];
            ldsm4(a0[0], a0[1], a0[2], a0[3], smaddr(Qs + (wid * 16 + ar) * QSTR + ks * 16 + ac));
#pragma unroll
            for (int ni = 0; ni < 8; ni++) mma16816(S[ni], a0, bf[ni]);
        }

        // S frags -> smem
        {
            int r = wid * 16 + (lane >> 2);
            int c = 2 * (lane & 3);
#pragma unroll
            for (int ni = 0; ni < 8; ni++) {
                Ss[r * SSTR + ni * 8 + c]           = S[ni][0];
                Ss[r * SSTR + ni * 8 + c + 1]       = S[ni][1];
                Ss[(r + 8) * SSTR + ni * 8 + c]     = S[ni][2];
                Ss[(r + 8) * SSTR + ni * 8 + c + 1] = S[ni][3];
            }
        }
        __syncthreads();

        // ---- online softmax (fp32, smem) ----
        {
            int r = tid >> 1, hf = tid & 1;
            const float* srow = Ss + r * SSTR + hf * 32;
            float sv[32], mx = -1e30f;
#pragma unroll
            for (int j = 0; j < 32; j++) { sv[j] = srow[j] + msk[hf * 32 + j]; mx = fmaxf(mx, sv[j]); }
            mx = fmaxf(mx, __shfl_xor_sync(0xffffffffu, mx, 1));
            float mold = mrow[r];
            float mnew = fmaxf(mold, mx);
            float scl = __expf(mold - mnew);
            float rs = 0.f;
#pragma unroll
            for (int j = 0; j < 32; j++) {
                float pf = __expf(sv[j] - mnew);
                rs += pf;
                __nv_bfloat16 hi, lo; bfsplit(pf, hi, lo);
                Ps[r * QSTR + hf * 32 + j]      = hi;
                Ps[r * QSTR + 64 + hf * 32 + j] = lo;
            }
            rs += __shfl_xor_sync(0xffffffffu, rs, 1);
            if (hf == 0) { lrow[r] = lrow[r] * scl + rs; mrow[r] = mnew; sclrow[r] = scl; }
        }
        __syncthreads();

        // rescale O by scl per row
        {
            int r1 = wid * 16 + (lane >> 2);
            float s1 = sclrow[r1], s2 = sclrow[r1 + 8];
#pragma unroll
            for (int ni = 0; ni < 8; ni++) {
                O[ni][0] *= s1; O[ni][1] *= s1; O[ni][2] *= s2; O[ni][3] *= s2;
            }
        }

        // ---- O += Phi*Vhi + Plo*Vhi + Phi*Vlo  (V via ldmatrix.trans) ----
#pragma unroll
        for (int ks = 0; ks < 4; ks++) {                 // B = Vhi
            uint32_t bf[8][2];
#pragma unroll
            for (int dp = 0; dp < 4; dp++) {
                uint32_t r0, r1, r2, r3;
                ldsm4t(r0, r1, r2, r3, smaddr(Vs + (ks * 16 + vr) * QSTR + dp * 16 + vc));
                bf[2 * dp][0] = r0; bf[2 * dp][1] = r1; bf[2 * dp + 1][0] = r2; bf[2 * dp + 1][1] = r3;
            }
            uint32_t a0[4], a1[4];
            ldsm4(a0[0], a0[1], a0[2], a0[3], smaddr(Ps + (wid * 16 + ar) * QSTR + ks * 16 + ac));
            ldsm4(a1[0], a1[1], a1[2], a1[3], smaddr(Ps + (wid * 16 + ar) * QSTR + 64 + ks * 16 + ac));
#pragma unroll
            for (int ni = 0; ni < 8; ni++) { mma16816(O[ni], a0, bf[ni]); mma16816(O[ni], a1, bf[ni]); }
        }
#pragma unroll
        for (int ks = 0; ks < 4; ks++) {                 // B = Vlo, A = Phi
            uint32_t bf[8][2];
#pragma unroll
            for (int dp = 0; dp < 4; dp++) {
                uint32_t r0, r1, r2, r3;
                ldsm4t(r0, r1, r2, r3, smaddr(Vs + (ks * 16 + vr) * QSTR + 64 + dp * 16 + vc));
                bf[2 * dp][0] = r0; bf[2 * dp][1] = r1; bf[2 * dp + 1][0] = r2; bf[2 * dp + 1][1] = r3;
            }
            uint32_t a0[4];
            ldsm4(a0[0], a0[1], a0[2], a0[3], smaddr(Ps + (wid * 16 + ar) * QSTR + ks * 16 + ac));
#pragma unroll
            for (int ni = 0; ni < 8; ni++) mma16816(O[ni], a0, bf[ni]);
        }
    }

    // epilogue: normalize, write out[b][s][h*64+d]
    {
        int r1 = wid * 16 + (lane >> 2);
        float i1 = 1.f / lrow[r1], i2 = 1.f / lrow[r1 + 8];
        int s1 = q0 + r1;
#pragma unroll
        for (int ni = 0; ni < 8; ni++) {
            int d = ni * 8 + 2 * (lane & 3);
            float2 v0 = make_float2(O[ni][0] * i1, O[ni][1] * i1);
            float2 v1 = make_float2(O[ni][2] * i2, O[ni][3] * i2);
            *(float2*)(out + ((size_t)(b * SEQ + s1) * HID) + h * 64 + d)     = v0;
            *(float2*)(out + ((size_t)(b * SEQ + s1 + 8) * HID) + h * 64 + d) = v1;
        }
    }
}

// ---------------------------------------------------------------------------
// Launch
// ---------------------------------------------------------------------------
extern "C" void kernel_launch(void* const* d_in, const int* in_sizes, int n_in,
                              void* d_out, int out_size) {
    (void)in_sizes; (void)n_in; (void)out_size;
    const float* x    = (const float*)d_in[0];
    const float* mask = (const float*)d_in[1];
    Ptrs3 W  = {{(const float*)d_in[2], (const float*)d_in[6],  (const float*)d_in[10]}};
    Ptrs3 bi = {{(const float*)d_in[3], (const float*)d_in[7],  (const float*)d_in[11]}};
    Ptrs3 A  = {{(const float*)d_in[4], (const float*)d_in[8],  (const float*)d_in[12]}};
    Ptrs3 Bl = {{(const float*)d_in[5], (const float*)d_in[9],  (const float*)d_in[13]}};
    float* out = (float*)d_out;

    fold_split_w<<<dim3((HID * HID) / 256, 3), 256>>>(W, A, Bl);
    split_x<<<(M_TOT * HID / 4) / 256, 256>>>(x);
    qkv_gemm_mma<<<dim3(HID / 64, M_TOT / 128, 3), 256>>>(bi);

    cudaFuncSetAttribute(flash_mma, cudaFuncAttributeMaxDynamicSharedMemorySize, ATTN_SMEM);
    flash_mma<<<dim3(SEQ / 64, NBH), 128, ATTN_SMEM>>>(mask, out);
}

// round 11
// speedup vs baseline: 3.0794x; 1.2753x over previous
#include <cuda_runtime.h>
#include <cuda_bf16.h>
#include <cstdint>

#define HID   1024
#define HEADS 16
#define HD    64
#define SEQ   2048
#define BATCH 4
#define NBH   (BATCH * HEADS)     // 64
#define M_TOT (BATCH * SEQ)       // 8192

// ---- static scratch (no cudaMalloc anywhere) ----
__device__ __align__(16) __nv_bfloat16 g_Whi[3 * HID * HID];
__device__ __align__(16) __nv_bfloat16 g_Wlo[3 * HID * HID];
__device__ __align__(16) __nv_bfloat16 g_Xhi[M_TOT * HID];
__device__ __align__(16) __nv_bfloat16 g_Xlo[M_TOT * HID];
// Q/K/V split: [mat][bh][s][128] (cols 0-63 = hi, 64-127 = lo); Q pre-scaled 0.125
__device__ __align__(16) __nv_bfloat16 g_QKVc[3][NBH * SEQ * 128];

struct Ptrs3 { const float* p[3]; };

// ---------------------------------------------------------------------------
// PTX helpers
// ---------------------------------------------------------------------------
__device__ __forceinline__ uint32_t smaddr(const void* p) {
    return (uint32_t)__cvta_generic_to_shared(p);
}
__device__ __forceinline__ void ldsm4(uint32_t& r0, uint32_t& r1, uint32_t& r2, uint32_t& r3, uint32_t a) {
    asm volatile("ldmatrix.sync.aligned.m8n8.x4.shared.b16 {%0,%1,%2,%3}, [%4];"
                 : "=r"(r0), "=r"(r1), "=r"(r2), "=r"(r3) : "r"(a));
}
__device__ __forceinline__ void ldsm4t(uint32_t& r0, uint32_t& r1, uint32_t& r2, uint32_t& r3, uint32_t a) {
    asm volatile("ldmatrix.sync.aligned.m8n8.x4.trans.shared.b16 {%0,%1,%2,%3}, [%4];"
                 : "=r"(r0), "=r"(r1), "=r"(r2), "=r"(r3) : "r"(a));
}
__device__ __forceinline__ void mma16816(float* c, const uint32_t* a, const uint32_t* b) {
    asm volatile("mma.sync.aligned.m16n8k16.row.col.f32.bf16.bf16.f32 "
                 "{%0,%1,%2,%3},{%4,%5,%6,%7},{%8,%9},{%0,%1,%2,%3};"
                 : "+f"(c[0]), "+f"(c[1]), "+f"(c[2]), "+f"(c[3])
                 : "r"(a[0]), "r"(a[1]), "r"(a[2]), "r"(a[3]), "r"(b[0]), "r"(b[1]));
}
__device__ __forceinline__ void bfsplit(float f, __nv_bfloat16& hi, __nv_bfloat16& lo) {
    hi = __float2bfloat16_rn(f);
    lo = __float2bfloat16_rn(f - __bfloat162float(hi));
}
__device__ __forceinline__ void cpa16(void* dst_smem, const void* src) {
    asm volatile("cp.async.cg.shared.global [%0], [%1], 16;"
                 :: "r"(smaddr(dst_smem)), "l"(src));
}
#define CPA_COMMIT() asm volatile("cp.async.commit_group;")
#define CPA_WAIT0()  asm volatile("cp.async.wait_group 0;")

// ---------------------------------------------------------------------------
// 1) Fold LoRA into W, split to bf16 hi/lo.  blockIdx.y = mat.
// ---------------------------------------------------------------------------
__global__ __launch_bounds__(256) void fold_split_w(Ptrs3 W, Ptrs3 A, Ptrs3 Bm) {
    const int mat = blockIdx.y;
    const float* __restrict__ Wp = W.p[mat];
    const float* __restrict__ Ap = A.p[mat];
    const float* __restrict__ Bp = Bm.p[mat];
    int idx = blockIdx.x * 256 + threadIdx.x;
    int i = idx >> 10, j = idx & 1023;
    float acc = 0.f;
#pragma unroll
    for (int r = 0; r < 16; r++)
        acc += Bp[(i << 4) + r] * Ap[(r << 10) + j];
    float w = Wp[idx] + acc * (1.0f / 16.0f);
    __nv_bfloat16 hi, lo; bfsplit(w, hi, lo);
    g_Whi[mat * HID * HID + idx] = hi;
    g_Wlo[mat * HID * HID + idx] = lo;
}

// ---------------------------------------------------------------------------
// 2) Split X (fp32 -> bf16 hi/lo)
// ---------------------------------------------------------------------------
__global__ __launch_bounds__(256) void split_x(const float* __restrict__ X) {
    int i4 = blockIdx.x * 256 + threadIdx.x;
    float4 v = ((const float4*)X)[i4];
    __nv_bfloat16 h[4], l[4];
    bfsplit(v.x, h[0], l[0]); bfsplit(v.y, h[1], l[1]);
    bfsplit(v.z, h[2], l[2]); bfsplit(v.w, h[3], l[3]);
    uint2 ph, pl;
    ph.x = (uint32_t)__bfloat16_as_ushort(h[0]) | ((uint32_t)__bfloat16_as_ushort(h[1]) << 16);
    ph.y = (uint32_t)__bfloat16_as_ushort(h[2]) | ((uint32_t)__bfloat16_as_ushort(h[3]) << 16);
    pl.x = (uint32_t)__bfloat16_as_ushort(l[0]) | ((uint32_t)__bfloat16_as_ushort(l[1]) << 16);
    pl.y = (uint32_t)__bfloat16_as_ushort(l[2]) | ((uint32_t)__bfloat16_as_ushort(l[3]) << 16);
    ((uint2*)g_Xhi)[i4] = ph;
    ((uint2*)g_Xlo)[i4] = pl;
}

// ---------------------------------------------------------------------------
// 3) QKV projection GEMM (bf16x3 mma) with 2-stage cp.async double buffering.
//    CTA 128m x 64n, BK=32, 8 warps (warp tile 32x32). blockIdx.z = mat.
// ---------------------------------------------------------------------------
#define ASTR   40                          // smem k-stride (bf16), 80B
#define GA_ELE (128 * ASTR)                // 5120
#define GB_ELE (64 * ASTR)                 // 2560
#define GSTAGE (2 * GA_ELE + 2 * GB_ELE)   // 15360 elems per stage
#define GEMM_SMEM (2 * GSTAGE * 2)         // 61440 bytes

__global__ __launch_bounds__(256) void qkv_gemm_mma(Ptrs3 bias) {
    extern __shared__ __align__(16) __nv_bfloat16 sg[];
    const int mat = blockIdx.z;
    const __nv_bfloat16* __restrict__ Whi = g_Whi + mat * HID * HID;
    const __nv_bfloat16* __restrict__ Wlo = g_Wlo + mat * HID * HID;

    const int tid = threadIdx.x, lane = tid & 31, wid = tid >> 5;
    const int m0 = blockIdx.y << 7, n0 = blockIdx.x << 6;
    const int wm = (wid >> 1) << 5;
    const int wn = (wid & 1) << 5;

    const int ar = (lane & 7) + ((lane & 8) ? 8 : 0);
    const int ac = (lane & 16) ? 8 : 0;
    const int br = (lane & 7) + ((lane >= 16) ? 8 : 0);
    const int bc = (lane & 8) ? 8 : 0;

    const int lrow = tid >> 2, lc8 = (tid & 3) << 3;

    auto issue = [&](int it, int st) {
        __nv_bfloat16* Ah = sg + st * GSTAGE;
        __nv_bfloat16* Al = Ah + GA_ELE;
        __nv_bfloat16* Bh = Al + GA_ELE;
        __nv_bfloat16* Bl = Bh + GB_ELE;
        int k0 = it << 5;
#pragma unroll
        for (int jj = 0; jj < 2; jj++) {
            int row = lrow + (jj << 6);
            cpa16(Ah + row * ASTR + lc8, g_Xhi + (size_t)(m0 + row) * HID + k0 + lc8);
            cpa16(Al + row * ASTR + lc8, g_Xlo + (size_t)(m0 + row) * HID + k0 + lc8);
        }
        cpa16(Bh + lrow * ASTR + lc8, Whi + (size_t)(n0 + lrow) * HID + k0 + lc8);
        cpa16(Bl + lrow * ASTR + lc8, Wlo + (size_t)(n0 + lrow) * HID + k0 + lc8);
    };

    float acc[2][4][4];
#pragma unroll
    for (int mi = 0; mi < 2; mi++)
#pragma unroll
        for (int ni = 0; ni < 4; ni++)
#pragma unroll
            for (int q = 0; q < 4; q++) acc[mi][ni][q] = 0.f;

    issue(0, 0); CPA_COMMIT();

    for (int it = 0; it < 32; it++) {
        CPA_WAIT0();
        __syncthreads();
        if (it < 31) { issue(it + 1, (it + 1) & 1); CPA_COMMIT(); }

        const __nv_bfloat16* Ah = sg + (it & 1) * GSTAGE;
        const __nv_bfloat16* Al = Ah + GA_ELE;
        const __nv_bfloat16* Bh = Al + GA_ELE;
        const __nv_bfloat16* Bl = Bh + GB_ELE;

#pragma unroll
        for (int ks = 0; ks < 2; ks++) {
            uint32_t af[2][4], alf[2][4], bf[4][2], blf[4][2];
#pragma unroll
            for (int mi = 0; mi < 2; mi++) {
                ldsm4(af[mi][0], af[mi][1], af[mi][2], af[mi][3],
                      smaddr(Ah + (wm + mi * 16 + ar) * ASTR + ks * 16 + ac));
                ldsm4(alf[mi][0], alf[mi][1], alf[mi][2], alf[mi][3],
                      smaddr(Al + (wm + mi * 16 + ar) * ASTR + ks * 16 + ac));
            }
#pragma unroll
            for (int p = 0; p < 2; p++) {
                uint32_t r0, r1, r2, r3;
                ldsm4(r0, r1, r2, r3, smaddr(Bh + (wn + p * 16 + br) * ASTR + ks * 16 + bc));
                bf[2 * p][0] = r0; bf[2 * p][1] = r1; bf[2 * p + 1][0] = r2; bf[2 * p + 1][1] = r3;
                ldsm4(r0, r1, r2, r3, smaddr(Bl + (wn + p * 16 + br) * ASTR + ks * 16 + bc));
                blf[2 * p][0] = r0; blf[2 * p][1] = r1; blf[2 * p + 1][0] = r2; blf[2 * p + 1][1] = r3;
            }
#pragma unroll
            for (int mi = 0; mi < 2; mi++)
#pragma unroll
                for (int ni = 0; ni < 4; ni++) {
                    mma16816(acc[mi][ni], af[mi],  bf[ni]);   // hi*hi
                    mma16816(acc[mi][ni], alf[mi], bf[ni]);   // lo*hi
                    mma16816(acc[mi][ni], af[mi],  blf[ni]);  // hi*lo
                }
        }
    }

    // epilogue: bias, optional Q scale, split, store [bh][s][128]
    const float* __restrict__ bp = bias.p[mat];
    const float qs = (mat == 0) ? 0.125f : 1.0f;
    __nv_bfloat16* __restrict__ outp = g_QKVc[mat];
#pragma unroll
    for (int mi = 0; mi < 2; mi++)
#pragma unroll
        for (int ni = 0; ni < 4; ni++) {
            int r = m0 + wm + mi * 16 + (lane >> 2);
            int c = n0 + wn + ni * 8 + 2 * (lane & 3);
            float b0 = bp[c], b1 = bp[c + 1];
            int hh = c >> 6, dd = c & 63;
#pragma unroll
            for (int h2 = 0; h2 < 2; h2++) {
                int rr = r + h2 * 8;
                int bb = rr >> 11, ss = rr & 2047;
                int bh = (bb << 4) + hh;
                float f0 = (acc[mi][ni][h2 * 2 + 0] + b0) * qs;
                float f1 = (acc[mi][ni][h2 * 2 + 1] + b1) * qs;
                __nv_bfloat16 h0, l0, h1, l1;
                bfsplit(f0, h0, l0); bfsplit(f1, h1, l1);
                uint32_t ph = (uint32_t)__bfloat16_as_ushort(h0) | ((uint32_t)__bfloat16_as_ushort(h1) << 16);
                uint32_t pl = (uint32_t)__bfloat16_as_ushort(l0) | ((uint32_t)__bfloat16_as_ushort(l1) << 16);
                size_t base = ((size_t)bh * SEQ + ss) * 128;
                *(uint32_t*)(outp + base + dd)      = ph;
                *(uint32_t*)(outp + base + 64 + dd) = pl;
            }
        }
}

// ---------------------------------------------------------------------------
// 4) Flash attention, FA-2 register dataflow (bf16x3 mma).
//    CTA = (64-q block, bh), 128 threads. Q in reg A-frags; softmax in regs
//    via quad shfl; P repacked in-register into A-frags. Smem = K,V only.
// ---------------------------------------------------------------------------
#define QSTR 136    // bf16 tile stride (272B)

__global__ __launch_bounds__(128, 3) void flash_mma(const float* __restrict__ mask,
                                                    float* __restrict__ out) {
    __shared__ __align__(16) __nv_bfloat16 Ks[64 * QSTR];
    __shared__ __align__(16) __nv_bfloat16 Vs[64 * QSTR];
    __shared__ float msk[64];

    const int tid = threadIdx.x, lane = tid & 31, wid = tid >> 5;
    const int bh = blockIdx.y, b = bh >> 4, h = bh & 15;
    const int q0 = blockIdx.x << 6;

    const __nv_bfloat16* __restrict__ Qg = g_QKVc[0] + (size_t)bh * SEQ * 128;
    const __nv_bfloat16* __restrict__ Kg = g_QKVc[1] + (size_t)bh * SEQ * 128;
    const __nv_bfloat16* __restrict__ Vg = g_QKVc[2] + (size_t)bh * SEQ * 128;

    const int ar = (lane & 7) + ((lane & 8) ? 8 : 0);
    const int ac = (lane & 16) ? 8 : 0;
    const int br = (lane & 7) + ((lane >= 16) ? 8 : 0);
    const int bc = (lane & 8) ? 8 : 0;
    const int vr = lane & 15;
    const int vc = (lane >= 16) ? 8 : 0;

    // stage Q through Ks, pull A-frags into regs (hi & lo, 4 k-blocks)
#pragma unroll
    for (int v = tid; v < 1024; v += 128) {
        int row = v >> 4, seg = (v & 15) << 3;
        *(uint4*)(Ks + row * QSTR + seg) = *(const uint4*)(Qg + (size_t)(q0 + row) * 128 + seg);
    }
    __syncthreads();
    uint32_t Qhi[4][4], Qlo[4][4];
#pragma unroll
    for (int ks = 0; ks < 4; ks++) {
        ldsm4(Qhi[ks][0], Qhi[ks][1], Qhi[ks][2], Qhi[ks][3],
              smaddr(Ks + (wid * 16 + ar) * QSTR + ks * 16 + ac));
        ldsm4(Qlo[ks][0], Qlo[ks][1], Qlo[ks][2], Qlo[ks][3],
              smaddr(Ks + (wid * 16 + ar) * QSTR + 64 + ks * 16 + ac));
    }
    __syncthreads();

    float O[8][4];
#pragma unroll
    for (int ni = 0; ni < 8; ni++)
#pragma unroll
        for (int q = 0; q < 4; q++) O[ni][q] = 0.f;
    float mr0 = -1e30f, mr1 = -1e30f, lr0 = 0.f, lr1 = 0.f;

    for (int kt = 0; kt < SEQ / 64; kt++) {
        const int s0 = kt * 64;
#pragma unroll
        for (int v = tid; v < 1024; v += 128) {
            int row = v >> 4, seg = (v & 15) << 3;
            *(uint4*)(Ks + row * QSTR + seg) = *(const uint4*)(Kg + (size_t)(s0 + row) * 128 + seg);
            *(uint4*)(Vs + row * QSTR + seg) = *(const uint4*)(Vg + (size_t)(s0 + row) * 128 + seg);
        }
        if (tid < 64) msk[tid] = mask[b * SEQ + s0 + tid];
        __syncthreads();

        // ---- S = Qhi*Khi + Qlo*Khi + Qhi*Klo ----
        float S[8][4];
#pragma unroll
        for (int ni = 0; ni < 8; ni++)
#pragma unroll
            for (int q = 0; q < 4; q++) S[ni][q] = 0.f;

#pragma unroll
        for (int ks = 0; ks < 4; ks++) {          // B = Khi
            uint32_t bf[8][2];
#pragma unroll
            for (int p = 0; p < 4; p++) {
                uint32_t r0, r1, r2, r3;
                ldsm4(r0, r1, r2, r3, smaddr(Ks + (p * 16 + br) * QSTR + ks * 16 + bc));
                bf[2 * p][0] = r0; bf[2 * p][1] = r1; bf[2 * p + 1][0] = r2; bf[2 * p + 1][1] = r3;
            }
#pragma unroll
            for (int ni = 0; ni < 8; ni++) {
                mma16816(S[ni], Qhi[ks], bf[ni]);
                mma16816(S[ni], Qlo[ks], bf[ni]);
            }
        }
#pragma unroll
        for (int ks = 0; ks < 4; ks++) {          // B = Klo, A = Qhi
            uint32_t bf[8][2];
#pragma unroll
            for (int p = 0; p < 4; p++) {
                uint32_t r0, r1, r2, r3;
                ldsm4(r0, r1, r2, r3, smaddr(Ks + (p * 16 + br) * QSTR + 64 + ks * 16 + bc));
                bf[2 * p][0] = r0; bf[2 * p][1] = r1; bf[2 * p + 1][0] = r2; bf[2 * p + 1][1] = r3;
            }
#pragma unroll
            for (int ni = 0; ni < 8; ni++) mma16816(S[ni], Qhi[ks], bf[ni]);
        }

        // ---- online softmax in registers (quad shfl row reductions) ----
        float mx0 = -1e30f, mx1 = -1e30f;
#pragma unroll
        for (int ni = 0; ni < 8; ni++) {
            float mc0 = msk[ni * 8 + 2 * (lane & 3)];
            float mc1 = msk[ni * 8 + 2 * (lane & 3) + 1];
            S[ni][0] += mc0; S[ni][1] += mc1; S[ni][2] += mc0; S[ni][3] += mc1;
            mx0 = fmaxf(mx0, fmaxf(S[ni][0], S[ni][1]));
            mx1 = fmaxf(mx1, fmaxf(S[ni][2], S[ni][3]));
        }
        mx0 = fmaxf(mx0, __shfl_xor_sync(0xffffffffu, mx0, 1));
        mx0 = fmaxf(mx0, __shfl_xor_sync(0xffffffffu, mx0, 2));
        mx1 = fmaxf(mx1, __shfl_xor_sync(0xffffffffu, mx1, 1));
        mx1 = fmaxf(mx1, __shfl_xor_sync(0xffffffffu, mx1, 2));
        float mn0 = fmaxf(mr0, mx0), mn1 = fmaxf(mr1, mx1);
        float scl0 = __expf(mr0 - mn0), scl1 = __expf(mr1 - mn1);
        mr0 = mn0; mr1 = mn1;

        float rs0 = 0.f, rs1 = 0.f;
        uint32_t PhiA[4][4], PloA[4][4];
#pragma unroll
        for (int ni = 0; ni < 8; ni++) {
            float p0 = __expf(S[ni][0] - mn0);
            float p1 = __expf(S[ni][1] - mn0);
            float p2 = __expf(S[ni][2] - mn1);
            float p3 = __expf(S[ni][3] - mn1);
            rs0 += p0 + p1; rs1 += p2 + p3;
            __nv_bfloat162 h01 = __floats2bfloat162_rn(p0, p1);
            __nv_bfloat162 h23 = __floats2bfloat162_rn(p2, p3);
            __nv_bfloat162 l01 = __floats2bfloat162_rn(p0 - __bfloat162float(h01.x),
                                                       p1 - __bfloat162float(h01.y));
            __nv_bfloat162 l23 = __floats2bfloat162_rn(p2 - __bfloat162float(h23.x),
                                                       p3 - __bfloat162float(h23.y));
            int kb = ni >> 1, off = (ni & 1) << 1;
            PhiA[kb][off]     = *(uint32_t*)&h01;
            PhiA[kb][off + 1] = *(uint32_t*)&h23;
            PloA[kb][off]     = *(uint32_t*)&l01;
            PloA[kb][off + 1] = *(uint32_t*)&l23;
        }
        rs0 += __shfl_xor_sync(0xffffffffu, rs0, 1);
        rs0 += __shfl_xor_sync(0xffffffffu, rs0, 2);
        rs1 += __shfl_xor_sync(0xffffffffu, rs1, 1);
        rs1 += __shfl_xor_sync(0xffffffffu, rs1, 2);
        lr0 = lr0 * scl0 + rs0;
        lr1 = lr1 * scl1 + rs1;
#pragma unroll
        for (int ni = 0; ni < 8; ni++) {
            O[ni][0] *= scl0; O[ni][1] *= scl0; O[ni][2] *= scl1; O[ni][3] *= scl1;
        }

        // ---- O += Phi*Vhi + Plo*Vhi + Phi*Vlo (V via ldmatrix.trans) ----
#pragma unroll
        for (int ks = 0; ks < 4; ks++) {          // B = Vhi
            uint32_t bf[8][2];
#pragma unroll
            for (int dp = 0; dp < 4; dp++) {
                uint32_t r0, r1, r2, r3;
                ldsm4t(r0, r1, r2, r3, smaddr(Vs + (ks * 16 + vr) * QSTR + dp * 16 + vc));
                bf[2 * dp][0] = r0; bf[2 * dp][1] = r1; bf[2 * dp + 1][0] = r2; bf[2 * dp + 1][1] = r3;
            }
#pragma unroll
            for (int ni = 0; ni < 8; ni++) {
                mma16816(O[ni], PhiA[ks], bf[ni]);
                mma16816(O[ni], PloA[ks], bf[ni]);
            }
        }
#pragma unroll
        for (int ks = 0; ks < 4; ks++) {          // B = Vlo, A = Phi
            uint32_t bf[8][2];
#pragma unroll
            for (int dp = 0; dp < 4; dp++) {
                uint32_t r0, r1, r2, r3;
                ldsm4t(r0, r1, r2, r3, smaddr(Vs + (ks * 16 + vr) * QSTR + 64 + dp * 16 + vc));
                bf[2 * dp][0] = r0; bf[2 * dp][1] = r1; bf[2 * dp + 1][0] = r2; bf[2 * dp + 1][1] = r3;
            }
#pragma unroll
            for (int ni = 0; ni < 8; ni++) mma16816(O[ni], PhiA[ks], bf[ni]);
        }
        __syncthreads();   // protect Ks/Vs/msk for next iteration's loads
    }

    // epilogue: normalize, write out[b][s][h*64+d]
    {
        float i0 = 1.f / lr0, i1 = 1.f / lr1;
        int s1 = q0 + wid * 16 + (lane >> 2);
#pragma unroll
        for (int ni = 0; ni < 8; ni++) {
            int d = ni * 8 + 2 * (lane & 3);
            float2 v0 = make_float2(O[ni][0] * i0, O[ni][1] * i0);
            float2 v1 = make_float2(O[ni][2] * i1, O[ni][3] * i1);
            *(float2*)(out + ((size_t)(b * SEQ + s1) * HID) + h * 64 + d)       = v0;
            *(float2*)(out + ((size_t)(b * SEQ + s1 + 8) * HID) + h * 64 + d)   = v1;
        }
    }
}

// ---------------------------------------------------------------------------
// Launch
// ---------------------------------------------------------------------------
extern "C" void kernel_launch(void* const* d_in, const int* in_sizes, int n_in,
                              void* d_out, int out_size) {
    (void)in_sizes; (void)n_in; (void)out_size;
    const float* x    = (const float*)d_in[0];
    const float* mask = (const float*)d_in[1];
    Ptrs3 W  = {{(const float*)d_in[2], (const float*)d_in[6],  (const float*)d_in[10]}};
    Ptrs3 bi = {{(const float*)d_in[3], (const float*)d_in[7],  (const float*)d_in[11]}};
    Ptrs3 A  = {{(const float*)d_in[4], (const float*)d_in[8],  (const float*)d_in[12]}};
    Ptrs3 Bl = {{(const float*)d_in[5], (const float*)d_in[9],  (const float*)d_in[13]}};
    float* out = (float*)d_out;

    fold_split_w<<<dim3((HID * HID) / 256, 3), 256>>>(W, A, Bl);
    split_x<<<(M_TOT * HID / 4) / 256, 256>>>(x);

    cudaFuncSetAttribute(qkv_gemm_mma, cudaFuncAttributeMaxDynamicSharedMemorySize, GEMM_SMEM);
    qkv_gemm_mma<<<dim3(HID / 64, M_TOT / 128, 3), 256, GEMM_SMEM>>>(bi);

    flash_mma<<<dim3(SEQ / 64, NBH), 128>>>(mask, out);
}

// round 13
// speedup vs baseline: 3.2646x; 1.0602x over previous
#include <cuda_runtime.h>
#include <cuda_bf16.h>
#include <cstdint>

#define HID   1024
#define HEADS 16
#define HD    64
#define SEQ   2048
#define BATCH 4
#define NBH   (BATCH * HEADS)     // 64
#define M_TOT (BATCH * SEQ)       // 8192

// ---- static scratch (no cudaMalloc anywhere) ----
__device__ __align__(16) __nv_bfloat16 g_Whi[3 * HID * HID];
__device__ __align__(16) __nv_bfloat16 g_Wlo[3 * HID * HID];
__device__ __align__(16) __nv_bfloat16 g_Xhi[M_TOT * HID];
__device__ __align__(16) __nv_bfloat16 g_Xlo[M_TOT * HID];
// Q/K/V split: [mat][bh][s][128] (cols 0-63 = hi, 64-127 = lo); Q pre-scaled 0.125
__device__ __align__(16) __nv_bfloat16 g_QKVc[3][NBH * SEQ * 128];

struct Ptrs3 { const float* p[3]; };

// ---------------------------------------------------------------------------
// PTX helpers
// ---------------------------------------------------------------------------
__device__ __forceinline__ uint32_t smaddr(const void* p) {
    return (uint32_t)__cvta_generic_to_shared(p);
}
__device__ __forceinline__ void ldsm4(uint32_t& r0, uint32_t& r1, uint32_t& r2, uint32_t& r3, uint32_t a) {
    asm volatile("ldmatrix.sync.aligned.m8n8.x4.shared.b16 {%0,%1,%2,%3}, [%4];"
                 : "=r"(r0), "=r"(r1), "=r"(r2), "=r"(r3) : "r"(a));
}
__device__ __forceinline__ void ldsm4t(uint32_t& r0, uint32_t& r1, uint32_t& r2, uint32_t& r3, uint32_t a) {
    asm volatile("ldmatrix.sync.aligned.m8n8.x4.trans.shared.b16 {%0,%1,%2,%3}, [%4];"
                 : "=r"(r0), "=r"(r1), "=r"(r2), "=r"(r3) : "r"(a));
}
__device__ __forceinline__ void mma16816(float* c, const uint32_t* a, const uint32_t* b) {
    asm volatile("mma.sync.aligned.m16n8k16.row.col.f32.bf16.bf16.f32 "
                 "{%0,%1,%2,%3},{%4,%5,%6,%7},{%8,%9},{%0,%1,%2,%3};"
                 : "+f"(c[0]), "+f"(c[1]), "+f"(c[2]), "+f"(c[3])
                 : "r"(a[0]), "r"(a[1]), "r"(a[2]), "r"(a[3]), "r"(b[0]), "r"(b[1]));
}
__device__ __forceinline__ void bfsplit(float f, __nv_bfloat16& hi, __nv_bfloat16& lo) {
    hi = __float2bfloat16_rn(f);
    lo = __float2bfloat16_rn(f - __bfloat162float(hi));
}
__device__ __forceinline__ void cpa16(void* dst_smem, const void* src) {
    asm volatile("cp.async.cg.shared.global [%0], [%1], 16;"
                 :: "r"(smaddr(dst_smem)), "l"(src));
}
#define CPA_COMMIT() asm volatile("cp.async.commit_group;")
#define CPA_WAIT0()  asm volatile("cp.async.wait_group 0;")

// ---------------------------------------------------------------------------
// 1) Fold LoRA into W, split to bf16 hi/lo.  blockIdx.y = mat.
// ---------------------------------------------------------------------------
__global__ __launch_bounds__(256) void fold_split_w(Ptrs3 W, Ptrs3 A, Ptrs3 Bm) {
    const int mat = blockIdx.y;
    const float* __restrict__ Wp = W.p[mat];
    const float* __restrict__ Ap = A.p[mat];
    const float* __restrict__ Bp = Bm.p[mat];
    int idx = blockIdx.x * 256 + threadIdx.x;
    int i = idx >> 10, j = idx & 1023;
    float acc = 0.f;
#pragma unroll
    for (int r = 0; r < 16; r++)
        acc += Bp[(i << 4) + r] * Ap[(r << 10) + j];
    float w = Wp[idx] + acc * (1.0f / 16.0f);
    __nv_bfloat16 hi, lo; bfsplit(w, hi, lo);
    g_Whi[mat * HID * HID + idx] = hi;
    g_Wlo[mat * HID * HID + idx] = lo;
}

// ---------------------------------------------------------------------------
// 2) Split X (fp32 -> bf16 hi/lo)
// ---------------------------------------------------------------------------
__global__ __launch_bounds__(256) void split_x(const float* __restrict__ X) {
    int i4 = blockIdx.x * 256 + threadIdx.x;
    float4 v = ((const float4*)X)[i4];
    __nv_bfloat16 h[4], l[4];
    bfsplit(v.x, h[0], l[0]); bfsplit(v.y, h[1], l[1]);
    bfsplit(v.z, h[2], l[2]); bfsplit(v.w, h[3], l[3]);
    uint2 ph, pl;
    ph.x = (uint32_t)__bfloat16_as_ushort(h[0]) | ((uint32_t)__bfloat16_as_ushort(h[1]) << 16);
    ph.y = (uint32_t)__bfloat16_as_ushort(h[2]) | ((uint32_t)__bfloat16_as_ushort(h[3]) << 16);
    pl.x = (uint32_t)__bfloat16_as_ushort(l[0]) | ((uint32_t)__bfloat16_as_ushort(l[1]) << 16);
    pl.y = (uint32_t)__bfloat16_as_ushort(l[2]) | ((uint32_t)__bfloat16_as_ushort(l[3]) << 16);
    ((uint2*)g_Xhi)[i4] = ph;
    ((uint2*)g_Xlo)[i4] = pl;
}

// ---------------------------------------------------------------------------
// 3) QKV projection GEMM (bf16x3 mma) with 2-stage cp.async double buffering.
//    CTA 128m x 64n, BK=32, 8 warps (warp tile 32x32). blockIdx.z = mat.
// ---------------------------------------------------------------------------
#define ASTR   40                          // smem k-stride (bf16), 80B
#define GA_ELE (128 * ASTR)                // 5120
#define GB_ELE (64 * ASTR)                 // 2560
#define GSTAGE (2 * GA_ELE + 2 * GB_ELE)   // 15360 elems per stage
#define GEMM_SMEM (2 * GSTAGE * 2)         // 61440 bytes

__global__ __launch_bounds__(256) void qkv_gemm_mma(Ptrs3 bias) {
    extern __shared__ __align__(16) __nv_bfloat16 sg[];
    const int mat = blockIdx.z;
    const __nv_bfloat16* __restrict__ Whi = g_Whi + mat * HID * HID;
    const __nv_bfloat16* __restrict__ Wlo = g_Wlo + mat * HID * HID;

    const int tid = threadIdx.x, lane = tid & 31, wid = tid >> 5;
    const int m0 = blockIdx.y << 7, n0 = blockIdx.x << 6;
    const int wm = (wid >> 1) << 5;
    const int wn = (wid & 1) << 5;

    const int ar = (lane & 7) + ((lane & 8) ? 8 : 0);
    const int ac = (lane & 16) ? 8 : 0;
    const int br = (lane & 7) + ((lane >= 16) ? 8 : 0);
    const int bc = (lane & 8) ? 8 : 0;

    const int lrow = tid >> 2, lc8 = (tid & 3) << 3;

    auto issue = [&](int it, int st) {
        __nv_bfloat16* Ah = sg + st * GSTAGE;
        __nv_bfloat16* Al = Ah + GA_ELE;
        __nv_bfloat16* Bh = Al + GA_ELE;
        __nv_bfloat16* Bl = Bh + GB_ELE;
        int k0 = it << 5;
#pragma unroll
        for (int jj = 0; jj < 2; jj++) {
            int row = lrow + (jj << 6);
            cpa16(Ah + row * ASTR + lc8, g_Xhi + (size_t)(m0 + row) * HID + k0 + lc8);
            cpa16(Al + row * ASTR + lc8, g_Xlo + (size_t)(m0 + row) * HID + k0 + lc8);
        }
        cpa16(Bh + lrow * ASTR + lc8, Whi + (size_t)(n0 + lrow) * HID + k0 + lc8);
        cpa16(Bl + lrow * ASTR + lc8, Wlo + (size_t)(n0 + lrow) * HID + k0 + lc8);
    };

    float acc[2][4][4];
#pragma unroll
    for (int mi = 0; mi < 2; mi++)
#pragma unroll
        for (int ni = 0; ni < 4; ni++)
#pragma unroll
            for (int q = 0; q < 4; q++) acc[mi][ni][q] = 0.f;

    issue(0, 0); CPA_COMMIT();

    for (int it = 0; it < 32; it++) {
        CPA_WAIT0();
        __syncthreads();
        if (it < 31) { issue(it + 1, (it + 1) & 1); CPA_COMMIT(); }

        const __nv_bfloat16* Ah = sg + (it & 1) * GSTAGE;
        const __nv_bfloat16* Al = Ah + GA_ELE;
        const __nv_bfloat16* Bh = Al + GA_ELE;
        const __nv_bfloat16* Bl = Bh + GB_ELE;

#pragma unroll
        for (int ks = 0; ks < 2; ks++) {
            uint32_t af[2][4], alf[2][4], bf[4][2], blf[4][2];
#pragma unroll
            for (int mi = 0; mi < 2; mi++) {
                ldsm4(af[mi][0], af[mi][1], af[mi][2], af[mi][3],
                      smaddr(Ah + (wm + mi * 16 + ar) * ASTR + ks * 16 + ac));
                ldsm4(alf[mi][0], alf[mi][1], alf[mi][2], alf[mi][3],
                      smaddr(Al + (wm + mi * 16 + ar) * ASTR + ks * 16 + ac));
            }
#pragma unroll
            for (int p = 0; p < 2; p++) {
                uint32_t r0, r1, r2, r3;
                ldsm4(r0, r1, r2, r3, smaddr(Bh + (wn + p * 16 + br) * ASTR + ks * 16 + bc));
                bf[2 * p][0] = r0; bf[2 * p][1] = r1; bf[2 * p + 1][0] = r2; bf[2 * p + 1][1] = r3;
                ldsm4(r0, r1, r2, r3, smaddr(Bl + (wn + p * 16 + br) * ASTR + ks * 16 + bc));
                blf[2 * p][0] = r0; blf[2 * p][1] = r1; blf[2 * p + 1][0] = r2; blf[2 * p + 1][1] = r3;
            }
#pragma unroll
            for (int mi = 0; mi < 2; mi++)
#pragma unroll
                for (int ni = 0; ni < 4; ni++) {
                    mma16816(acc[mi][ni], af[mi],  bf[ni]);   // hi*hi
                    mma16816(acc[mi][ni], alf[mi], bf[ni]);   // lo*hi
                    mma16816(acc[mi][ni], af[mi],  blf[ni]);  // hi*lo
                }
        }
    }

    // epilogue: bias, optional Q scale, split, store [bh][s][128]
    const float* __restrict__ bp = bias.p[mat];
    const float qs = (mat == 0) ? 0.125f : 1.0f;
    __nv_bfloat16* __restrict__ outp = g_QKVc[mat];
#pragma unroll
    for (int mi = 0; mi < 2; mi++)
#pragma unroll
        for (int ni = 0; ni < 4; ni++) {
            int r = m0 + wm + mi * 16 + (lane >> 2);
            int c = n0 + wn + ni * 8 + 2 * (lane & 3);
            float b0 = bp[c], b1 = bp[c + 1];
            int hh = c >> 6, dd = c & 63;
#pragma unroll
            for (int h2 = 0; h2 < 2; h2++) {
                int rr = r + h2 * 8;
                int bb = rr >> 11, ss = rr & 2047;
                int bh = (bb << 4) + hh;
                float f0 = (acc[mi][ni][h2 * 2 + 0] + b0) * qs;
                float f1 = (acc[mi][ni][h2 * 2 + 1] + b1) * qs;
                __nv_bfloat16 h0, l0, h1, l1;
                bfsplit(f0, h0, l0); bfsplit(f1, h1, l1);
                uint32_t ph = (uint32_t)__bfloat16_as_ushort(h0) | ((uint32_t)__bfloat16_as_ushort(h1) << 16);
                uint32_t pl = (uint32_t)__bfloat16_as_ushort(l0) | ((uint32_t)__bfloat16_as_ushort(l1) << 16);
                size_t base = ((size_t)bh * SEQ + ss) * 128;
                *(uint32_t*)(outp + base + dd)      = ph;
                *(uint32_t*)(outp + base + 64 + dd) = pl;
            }
        }
}

// ---------------------------------------------------------------------------
// 4) Flash attention, FA-2 register dataflow (bf16x3 mma) with 2-stage
//    cp.async K/V double buffering. CTA = (64-q block, bh), 128 threads.
//    Q in reg A-frags; softmax in regs; P repacked in-register. 1 bar/iter.
// ---------------------------------------------------------------------------
#define QSTR 136                          // bf16 tile stride (272B)
#define FSTAGE_E (2 * 64 * QSTR)          // K+V elems per stage (17408)
#define FSTAGE_B (FSTAGE_E * 2)           // 34816 bytes
#define FLASH_SMEM (2 * FSTAGE_B + 2 * 64 * 4)  // 70144 bytes

__global__ __launch_bounds__(128, 3) void flash_mma(const float* __restrict__ mask,
                                                    float* __restrict__ out) {
    extern __shared__ __align__(16) char smbuf[];
    __nv_bfloat16* KVbase = (__nv_bfloat16*)smbuf;
    float* msk2 = (float*)(smbuf + 2 * FSTAGE_B);   // [2][64]

    const int tid = threadIdx.x, lane = tid & 31, wid = tid >> 5;
    const int bh = blockIdx.y, b = bh >> 4, h = bh & 15;
    const int q0 = blockIdx.x << 6;

    const __nv_bfloat16* __restrict__ Qg = g_QKVc[0] + (size_t)bh * SEQ * 128;
    const __nv_bfloat16* __restrict__ Kg = g_QKVc[1] + (size_t)bh * SEQ * 128;
    const __nv_bfloat16* __restrict__ Vg = g_QKVc[2] + (size_t)bh * SEQ * 128;
    const float* __restrict__ mg = mask + b * SEQ;

    const int ar = (lane & 7) + ((lane & 8) ? 8 : 0);
    const int ac = (lane & 16) ? 8 : 0;
    const int br = (lane & 7) + ((lane >= 16) ? 8 : 0);
    const int bc = (lane & 8) ? 8 : 0;
    const int vr = lane & 15;
    const int vc = (lane >= 16) ? 8 : 0;

    auto issue_kv = [&](int kt, int st) {
        __nv_bfloat16* Kd = KVbase + st * FSTAGE_E;
        __nv_bfloat16* Vd = Kd + 64 * QSTR;
        const __nv_bfloat16* Kt = Kg + (size_t)(kt << 6) * 128;
        const __nv_bfloat16* Vt = Vg + (size_t)(kt << 6) * 128;
#pragma unroll
        for (int v = tid; v < 1024; v += 128) {
            int row = v >> 4, seg = (v & 15) << 3;
            cpa16(Kd + row * QSTR + seg, Kt + row * 128 + seg);
            cpa16(Vd + row * QSTR + seg, Vt + row * 128 + seg);
        }
        if (tid < 16) cpa16(msk2 + st * 64 + tid * 4, mg + (kt << 6) + tid * 4);
    };

    // start prefetch of tile 0 into stage 0; stage Q through stage 1's buffer
    issue_kv(0, 0); CPA_COMMIT();
    {
        __nv_bfloat16* Qstage = KVbase + 1 * FSTAGE_E;
#pragma unroll
        for (int v = tid; v < 1024; v += 128) {
            int row = v >> 4, seg = (v & 15) << 3;
            *(uint4*)(Qstage + row * QSTR + seg) = *(const uint4*)(Qg + (size_t)(q0 + row) * 128 + seg);
        }
    }
    __syncthreads();
    uint32_t Qhi[4][4], Qlo[4][4];
    {
        const __nv_bfloat16* Qstage = KVbase + 1 * FSTAGE_E;
#pragma unroll
        for (int ks = 0; ks < 4; ks++) {
            ldsm4(Qhi[ks][0], Qhi[ks][1], Qhi[ks][2], Qhi[ks][3],
                  smaddr(Qstage + (wid * 16 + ar) * QSTR + ks * 16 + ac));
            ldsm4(Qlo[ks][0], Qlo[ks][1], Qlo[ks][2], Qlo[ks][3],
                  smaddr(Qstage + (wid * 16 + ar) * QSTR + 64 + ks * 16 + ac));
        }
    }
    __syncthreads();   // all warps done reading stage 1 before tile-1 prefetch

    float O[8][4];
#pragma unroll
    for (int ni = 0; ni < 8; ni++)
#pragma unroll
        for (int q = 0; q < 4; q++) O[ni][q] = 0.f;
    float mr0 = -1e30f, mr1 = -1e30f, lr0 = 0.f, lr1 = 0.f;

    for (int kt = 0; kt < SEQ / 64; kt++) {
        CPA_WAIT0();
        __syncthreads();
        if (kt < SEQ / 64 - 1) { issue_kv(kt + 1, (kt + 1) & 1); CPA_COMMIT(); }

        const __nv_bfloat16* Ks = KVbase + (kt & 1) * FSTAGE_E;
        const __nv_bfloat16* Vs = Ks + 64 * QSTR;
        const float* mskp = msk2 + (kt & 1) * 64;

        // ---- S = Qhi*Khi + Qlo*Khi + Qhi*Klo ----
        float S[8][4];
#pragma unroll
        for (int ni = 0; ni < 8; ni++)
#pragma unroll
            for (int q = 0; q < 4; q++) S[ni][q] = 0.f;

#pragma unroll
        for (int ks = 0; ks < 4; ks++) {          // B = Khi
            uint32_t bf[8][2];
#pragma unroll
            for (int p = 0; p < 4; p++) {
                uint32_t r0, r1, r2, r3;
                ldsm4(r0, r1, r2, r3, smaddr(Ks + (p * 16 + br) * QSTR + ks * 16 + bc));
                bf[2 * p][0] = r0; bf[2 * p][1] = r1; bf[2 * p + 1][0] = r2; bf[2 * p + 1][1] = r3;
            }
#pragma unroll
            for (int ni = 0; ni < 8; ni++) {
                mma16816(S[ni], Qhi[ks], bf[ni]);
                mma16816(S[ni], Qlo[ks], bf[ni]);
            }
        }
#pragma unroll
        for (int ks = 0; ks < 4; ks++) {          // B = Klo, A = Qhi
            uint32_t bf[8][2];
#pragma unroll
            for (int p = 0; p < 4; p++) {
                uint32_t r0, r1, r2, r3;
                ldsm4(r0, r1, r2, r3, smaddr(Ks + (p * 16 + br) * QSTR + 64 + ks * 16 + bc));
                bf[2 * p][0] = r0; bf[2 * p][1] = r1; bf[2 * p + 1][0] = r2; bf[2 * p + 1][1] = r3;
            }
#pragma unroll
            for (int ni = 0; ni < 8; ni++) mma16816(S[ni], Qhi[ks], bf[ni]);
        }

        // ---- online softmax in registers (quad shfl row reductions) ----
        float mx0 = -1e30f, mx1 = -1e30f;
#pragma unroll
        for (int ni = 0; ni < 8; ni++) {
            float mc0 = mskp[ni * 8 + 2 * (lane & 3)];
            float mc1 = mskp[ni * 8 + 2 * (lane & 3) + 1];
            S[ni][0] += mc0; S[ni][1] += mc1; S[ni][2] += mc0; S[ni][3] += mc1;
            mx0 = fmaxf(mx0, fmaxf(S[ni][0], S[ni][1]));
            mx1 = fmaxf(mx1, fmaxf(S[ni][2], S[ni][3]));
        }
        mx0 = fmaxf(mx0, __shfl_xor_sync(0xffffffffu, mx0, 1));
        mx0 = fmaxf(mx0, __shfl_xor_sync(0xffffffffu, mx0, 2));
        mx1 = fmaxf(mx1, __shfl_xor_sync(0xffffffffu, mx1, 1));
        mx1 = fmaxf(mx1, __shfl_xor_sync(0xffffffffu, mx1, 2));
        float mn0 = fmaxf(mr0, mx0), mn1 = fmaxf(mr1, mx1);
        float scl0 = __expf(mr0 - mn0), scl1 = __expf(mr1 - mn1);
        mr0 = mn0; mr1 = mn1;

        float rs0 = 0.f, rs1 = 0.f;
        uint32_t PhiA[4][4], PloA[4][4];
#pragma unroll
        for (int ni = 0; ni < 8; ni++) {
            float p0 = __expf(S[ni][0] - mn0);
            float p1 = __expf(S[ni][1] - mn0);
            float p2 = __expf(S[ni][2] - mn1);
            float p3 = __expf(S[ni][3] - mn1);
            rs0 += p0 + p1; rs1 += p2 + p3;
            __nv_bfloat162 h01 = __floats2bfloat162_rn(p0, p1);
            __nv_bfloat162 h23 = __floats2bfloat162_rn(p2, p3);
            __nv_bfloat162 l01 = __floats2bfloat162_rn(p0 - __bfloat162float(h01.x),
                                                       p1 - __bfloat162float(h01.y));
            __nv_bfloat162 l23 = __floats2bfloat162_rn(p2 - __bfloat162float(h23.x),
                                                       p3 - __bfloat162float(h23.y));
            int kb = ni >> 1, off = (ni & 1) << 1;
            PhiA[kb][off]     = *(uint32_t*)&h01;
            PhiA[kb][off + 1] = *(uint32_t*)&h23;
            PloA[kb][off]     = *(uint32_t*)&l01;
            PloA[kb][off + 1] = *(uint32_t*)&l23;
        }
        rs0 += __shfl_xor_sync(0xffffffffu, rs0, 1);
        rs0 += __shfl_xor_sync(0xffffffffu, rs0, 2);
        rs1 += __shfl_xor_sync(0xffffffffu, rs1, 1);
        rs1 += __shfl_xor_sync(0xffffffffu, rs1, 2);
        lr0 = lr0 * scl0 + rs0;
        lr1 = lr1 * scl1 + rs1;
#pragma unroll
        for (int ni = 0; ni < 8; ni++) {
            O[ni][0] *= scl0; O[ni][1] *= scl0; O[ni][2] *= scl1; O[ni][3] *= scl1;
        }

        // ---- O += Phi*Vhi + Plo*Vhi + Phi*Vlo (V via ldmatrix.trans) ----
#pragma unroll
        for (int ks = 0; ks < 4; ks++) {          // B = Vhi
            uint32_t bf[8][2];
#pragma unroll
            for (int dp = 0; dp < 4; dp++) {
                uint32_t r0, r1, r2, r3;
                ldsm4t(r0, r1, r2, r3, smaddr(Vs + (ks * 16 + vr) * QSTR + dp * 16 + vc));
                bf[2 * dp][0] = r0; bf[2 * dp][1] = r1; bf[2 * dp + 1][0] = r2; bf[2 * dp + 1][1] = r3;
            }
#pragma unroll
            for (int ni = 0; ni < 8; ni++) {
                mma16816(O[ni], PhiA[ks], bf[ni]);
                mma16816(O[ni], PloA[ks], bf[ni]);
            }
        }
#pragma unroll
        for (int ks = 0; ks < 4; ks++) {          // B = Vlo, A = Phi
            uint32_t bf[8][2];
#pragma unroll
            for (int dp = 0; dp < 4; dp++) {
                uint32_t r0, r1, r2, r3;
                ldsm4t(r0, r1, r2, r3, smaddr(Vs + (ks * 16 + vr) * QSTR + 64 + dp * 16 + vc));
                bf[2 * dp][0] = r0; bf[2 * dp][1] = r1; bf[2 * dp + 1][0] = r2; bf[2 * dp + 1][1] = r3;
            }
#pragma unroll
            for (int ni = 0; ni < 8; ni++) mma16816(O[ni], PhiA[ks], bf[ni]);
        }
        // no bottom barrier: next iteration's top wait+barrier covers hazards
    }

    // epilogue: normalize, write out[b][s][h*64+d]
    {
        float i0 = 1.f / lr0, i1 = 1.f / lr1;
        int s1 = q0 + wid * 16 + (lane >> 2);
#pragma unroll
        for (int ni = 0; ni < 8; ni++) {
            int d = ni * 8 + 2 * (lane & 3);
            float2 v0 = make_float2(O[ni][0] * i0, O[ni][1] * i0);
            float2 v1 = make_float2(O[ni][2] * i1, O[ni][3] * i1);
            *(float2*)(out + ((size_t)(b * SEQ + s1) * HID) + h * 64 + d)     = v0;
            *(float2*)(out + ((size_t)(b * SEQ + s1 + 8) * HID) + h * 64 + d) = v1;
        }
    }
}

// ---------------------------------------------------------------------------
// Launch
// ---------------------------------------------------------------------------
extern "C" void kernel_launch(void* const* d_in, const int* in_sizes, int n_in,
                              void* d_out, int out_size) {
    (void)in_sizes; (void)n_in; (void)out_size;
    const float* x    = (const float*)d_in[0];
    const float* mask = (const float*)d_in[1];
    Ptrs3 W  = {{(const float*)d_in[2], (const float*)d_in[6],  (const float*)d_in[10]}};
    Ptrs3 bi = {{(const float*)d_in[3], (const float*)d_in[7],  (const float*)d_in[11]}};
    Ptrs3 A  = {{(const float*)d_in[4], (const float*)d_in[8],  (const float*)d_in[12]}};
    Ptrs3 Bl = {{(const float*)d_in[5], (const float*)d_in[9],  (const float*)d_in[13]}};
    float* out = (float*)d_out;

    fold_split_w<<<dim3((HID * HID) / 256, 3), 256>>>(W, A, Bl);
    split_x<<<(M_TOT * HID / 4) / 256, 256>>>(x);

    cudaFuncSetAttribute(qkv_gemm_mma, cudaFuncAttributeMaxDynamicSharedMemorySize, GEMM_SMEM);
    qkv_gemm_mma<<<dim3(HID / 64, M_TOT / 128, 3), 256, GEMM_SMEM>>>(bi);

    cudaFuncSetAttribute(flash_mma, cudaFuncAttributeMaxDynamicSharedMemorySize, FLASH_SMEM);
    flash_mma<<<dim3(SEQ / 64, NBH), 128, FLASH_SMEM>>>(mask, out);
}

// round 16
// speedup vs baseline: 3.3436x; 1.0242x over previous
#include <cuda_runtime.h>
#include <cuda_bf16.h>
#include <cstdint>

#define HID   1024
#define HEADS 16
#define HD    64
#define SEQ   2048
#define BATCH 4
#define NBH   (BATCH * HEADS)     // 64
#define M_TOT (BATCH * SEQ)       // 8192

// ---- static scratch (no cudaMalloc anywhere) ----
__device__ __align__(16) __nv_bfloat16 g_Whi[3 * HID * HID];
__device__ __align__(16) __nv_bfloat16 g_Wlo[3 * HID * HID];
__device__ __align__(16) __nv_bfloat16 g_Xhi[M_TOT * HID];
__device__ __align__(16) __nv_bfloat16 g_Xlo[M_TOT * HID];
// Q/K/V split: [mat][bh][s][128] (cols 0-63 = hi, 64-127 = lo); Q pre-scaled 0.125
__device__ __align__(16) __nv_bfloat16 g_QKVc[3][NBH * SEQ * 128];

struct Ptrs3 { const float* p[3]; };

// ---------------------------------------------------------------------------
// PTX helpers (legacy sm_103-legal only: ldmatrix / mma.sync / cp.async)
// ---------------------------------------------------------------------------
__device__ __forceinline__ uint32_t smaddr(const void* p) {
    return (uint32_t)__cvta_generic_to_shared(p);
}
__device__ __forceinline__ void ldsm4(uint32_t& r0, uint32_t& r1, uint32_t& r2, uint32_t& r3, uint32_t a) {
    asm volatile("ldmatrix.sync.aligned.m8n8.x4.shared.b16 {%0,%1,%2,%3}, [%4];"
                 : "=r"(r0), "=r"(r1), "=r"(r2), "=r"(r3) : "r"(a));
}
__device__ __forceinline__ void ldsm4t(uint32_t& r0, uint32_t& r1, uint32_t& r2, uint32_t& r3, uint32_t a) {
    asm volatile("ldmatrix.sync.aligned.m8n8.x4.trans.shared.b16 {%0,%1,%2,%3}, [%4];"
                 : "=r"(r0), "=r"(r1), "=r"(r2), "=r"(r3) : "r"(a));
}
__device__ __forceinline__ void mma16816(float* c, const uint32_t* a, const uint32_t* b) {
    asm volatile("mma.sync.aligned.m16n8k16.row.col.f32.bf16.bf16.f32 "
                 "{%0,%1,%2,%3},{%4,%5,%6,%7},{%8,%9},{%0,%1,%2,%3};"
                 : "+f"(c[0]), "+f"(c[1]), "+f"(c[2]), "+f"(c[3])
                 : "r"(a[0]), "r"(a[1]), "r"(a[2]), "r"(a[3]), "r"(b[0]), "r"(b[1]));
}
__device__ __forceinline__ void bfsplit(float f, __nv_bfloat16& hi, __nv_bfloat16& lo) {
    hi = __float2bfloat16_rn(f);
    lo = __float2bfloat16_rn(f - __bfloat162float(hi));
}
__device__ __forceinline__ void cpa16(void* dst_smem, const void* src) {
    asm volatile("cp.async.cg.shared.global [%0], [%1], 16;"
                 :: "r"(smaddr(dst_smem)), "l"(src));
}
#define CPA_COMMIT() asm volatile("cp.async.commit_group;")
#define CPA_WAIT0()  asm volatile("cp.async.wait_group 0;")

// ---------------------------------------------------------------------------
// 1) Fold LoRA into W, split to bf16 hi/lo.  blockIdx.y = mat.
// ---------------------------------------------------------------------------
__global__ __launch_bounds__(256) void fold_split_w(Ptrs3 W, Ptrs3 A, Ptrs3 Bm) {
    const int mat = blockIdx.y;
    const float* __restrict__ Wp = W.p[mat];
    const float* __restrict__ Ap = A.p[mat];
    const float* __restrict__ Bp = Bm.p[mat];
    int idx = blockIdx.x * 256 + threadIdx.x;
    int i = idx >> 10, j = idx & 1023;
    float acc = 0.f;
#pragma unroll
    for (int r = 0; r < 16; r++)
        acc += Bp[(i << 4) + r] * Ap[(r << 10) + j];
    float w = Wp[idx] + acc * (1.0f / 16.0f);
    __nv_bfloat16 hi, lo; bfsplit(w, hi, lo);
    g_Whi[mat * HID * HID + idx] = hi;
    g_Wlo[mat * HID * HID + idx] = lo;
}

// ---------------------------------------------------------------------------
// 2) Split X (fp32 -> bf16 hi/lo)
// ---------------------------------------------------------------------------
__global__ __launch_bounds__(256) void split_x(const float* __restrict__ X) {
    int i4 = blockIdx.x * 256 + threadIdx.x;
    float4 v = ((const float4*)X)[i4];
    __nv_bfloat16 h[4], l[4];
    bfsplit(v.x, h[0], l[0]); bfsplit(v.y, h[1], l[1]);
    bfsplit(v.z, h[2], l[2]); bfsplit(v.w, h[3], l[3]);
    uint2 ph, pl;
    ph.x = (uint32_t)__bfloat16_as_ushort(h[0]) | ((uint32_t)__bfloat16_as_ushort(h[1]) << 16);
    ph.y = (uint32_t)__bfloat16_as_ushort(h[2]) | ((uint32_t)__bfloat16_as_ushort(h[3]) << 16);
    pl.x = (uint32_t)__bfloat16_as_ushort(l[0]) | ((uint32_t)__bfloat16_as_ushort(l[1]) << 16);
    pl.y = (uint32_t)__bfloat16_as_ushort(l[2]) | ((uint32_t)__bfloat16_as_ushort(l[3]) << 16);
    ((uint2*)g_Xhi)[i4] = ph;
    ((uint2*)g_Xlo)[i4] = pl;
}

// ---------------------------------------------------------------------------
// 3) QKV projection GEMM (bf16x3 mma) with 2-stage cp.async double buffering.
//    CTA 128m x 128n, BK=32, 8 warps (warp tile 32x64, 4x2 layout).
//    blockIdx.z = mat.  Epilogue writes split bf16 Q/K/V in [bh][s][128].
// ---------------------------------------------------------------------------
#define ASTR   40                          // smem k-stride (bf16), 80B
#define GT_ELE (128 * ASTR)                // 5120 elems per 128x32 tile buffer
#define GSTAGE (4 * GT_ELE)                // Ah,Al,Bh,Bl per stage (20480 elems)
#define GEMM_SMEM (2 * GSTAGE * 2)         // 81920 bytes

__global__ __launch_bounds__(256, 2) void qkv_gemm_mma(Ptrs3 bias) {
    extern __shared__ __align__(16) __nv_bfloat16 sg[];
    const int mat = blockIdx.z;
    const __nv_bfloat16* __restrict__ Whi = g_Whi + mat * HID * HID;
    const __nv_bfloat16* __restrict__ Wlo = g_Wlo + mat * HID * HID;

    const int tid = threadIdx.x, lane = tid & 31, wid = tid >> 5;
    const int m0 = blockIdx.y << 7, n0 = blockIdx.x << 7;
    const int wm = (wid >> 1) << 5;      // warp row offset (0,32,64,96)
    const int wn = (wid & 1) << 6;       // warp col offset (0,64)

    const int ar = (lane & 7) + ((lane & 8) ? 8 : 0);
    const int ac = (lane & 16) ? 8 : 0;
    const int br = (lane & 7) + ((lane >= 16) ? 8 : 0);
    const int bc = (lane & 8) ? 8 : 0;

    auto issue = [&](int it, int st) {
        __nv_bfloat16* Ah = sg + st * GSTAGE;
        __nv_bfloat16* Al = Ah + GT_ELE;
        __nv_bfloat16* Bh = Al + GT_ELE;
        __nv_bfloat16* Bl = Bh + GT_ELE;
        int k0 = it << 5;
#pragma unroll
        for (int jj = 0; jj < 2; jj++) {
            int v = tid + jj * 256;                 // 0..511 (128 rows x 4 pieces)
            int row = v >> 2, c8 = (v & 3) << 3;
            cpa16(Ah + row * ASTR + c8, g_Xhi + (size_t)(m0 + row) * HID + k0 + c8);
            cpa16(Al + row * ASTR + c8, g_Xlo + (size_t)(m0 + row) * HID + k0 + c8);
            cpa16(Bh + row * ASTR + c8, Whi + (size_t)(n0 + row) * HID + k0 + c8);
            cpa16(Bl + row * ASTR + c8, Wlo + (size_t)(n0 + row) * HID + k0 + c8);
        }
    };

    float acc[2][8][4];
#pragma unroll
    for (int mi = 0; mi < 2; mi++)
#pragma unroll
        for (int ni = 0; ni < 8; ni++)
#pragma unroll
            for (int q = 0; q < 4; q++) acc[mi][ni][q] = 0.f;

    issue(0, 0); CPA_COMMIT();

    for (int it = 0; it < 32; it++) {
        CPA_WAIT0();
        __syncthreads();
        if (it < 31) { issue(it + 1, (it + 1) & 1); CPA_COMMIT(); }

        const __nv_bfloat16* Ah = sg + (it & 1) * GSTAGE;
        const __nv_bfloat16* Al = Ah + GT_ELE;
        const __nv_bfloat16* Bh = Al + GT_ELE;
        const __nv_bfloat16* Bl = Bh + GT_ELE;

#pragma unroll
        for (int ks = 0; ks < 2; ks++) {
            uint32_t af[2][4], alf[2][4], bf[8][2];
#pragma unroll
            for (int mi = 0; mi < 2; mi++) {
                ldsm4(af[mi][0], af[mi][1], af[mi][2], af[mi][3],
                      smaddr(Ah + (wm + mi * 16 + ar) * ASTR + ks * 16 + ac));
                ldsm4(alf[mi][0], alf[mi][1], alf[mi][2], alf[mi][3],
                      smaddr(Al + (wm + mi * 16 + ar) * ASTR + ks * 16 + ac));
            }
            // B = Whi frags (64 cols): hi*hi + lo*hi
#pragma unroll
            for (int p = 0; p < 4; p++) {
                uint32_t r0, r1, r2, r3;
                ldsm4(r0, r1, r2, r3, smaddr(Bh + (wn + p * 16 + br) * ASTR + ks * 16 + bc));
                bf[2 * p][0] = r0; bf[2 * p][1] = r1; bf[2 * p + 1][0] = r2; bf[2 * p + 1][1] = r3;
            }
#pragma unroll
            for (int mi = 0; mi < 2; mi++)
#pragma unroll
                for (int ni = 0; ni < 8; ni++) {
                    mma16816(acc[mi][ni], af[mi],  bf[ni]);   // hi*hi
                    mma16816(acc[mi][ni], alf[mi], bf[ni]);   // lo*hi
                }
            // B = Wlo frags (reuse bf regs): hi*lo
#pragma unroll
            for (int p = 0; p < 4; p++) {
                uint32_t r0, r1, r2, r3;
                ldsm4(r0, r1, r2, r3, smaddr(Bl + (wn + p * 16 + br) * ASTR + ks * 16 + bc));
                bf[2 * p][0] = r0; bf[2 * p][1] = r1; bf[2 * p + 1][0] = r2; bf[2 * p + 1][1] = r3;
            }
#pragma unroll
            for (int mi = 0; mi < 2; mi++)
#pragma unroll
                for (int ni = 0; ni < 8; ni++)
                    mma16816(acc[mi][ni], af[mi], bf[ni]);    // hi*lo
        }
    }

    // epilogue: bias, optional Q scale, split, store [bh][s][128]
    const float* __restrict__ bp = bias.p[mat];
    const float qs = (mat == 0) ? 0.125f : 1.0f;
    __nv_bfloat16* __restrict__ outp = g_QKVc[mat];
#pragma unroll
    for (int mi = 0; mi < 2; mi++)
#pragma unroll
        for (int ni = 0; ni < 8; ni++) {
            int r = m0 + wm + mi * 16 + (lane >> 2);
            int c = n0 + wn + ni * 8 + 2 * (lane & 3);
            float b0 = bp[c], b1 = bp[c + 1];
            int hh = c >> 6, dd = c & 63;
#pragma unroll
            for (int h2 = 0; h2 < 2; h2++) {
                int rr = r + h2 * 8;
                int bb = rr >> 11, ss = rr & 2047;
                int bh = (bb << 4) + hh;
                float f0 = (acc[mi][ni][h2 * 2 + 0] + b0) * qs;
                float f1 = (acc[mi][ni][h2 * 2 + 1] + b1) * qs;
                __nv_bfloat16 h0, l0, h1, l1;
                bfsplit(f0, h0, l0); bfsplit(f1, h1, l1);
                uint32_t ph = (uint32_t)__bfloat16_as_ushort(h0) | ((uint32_t)__bfloat16_as_ushort(h1) << 16);
                uint32_t pl = (uint32_t)__bfloat16_as_ushort(l0) | ((uint32_t)__bfloat16_as_ushort(l1) << 16);
                size_t base = ((size_t)bh * SEQ + ss) * 128;
                *(uint32_t*)(outp + base + dd)      = ph;
                *(uint32_t*)(outp + base + 64 + dd) = pl;
            }
        }
}

// ---------------------------------------------------------------------------
// 4) Flash attention, FA-2 register dataflow (bf16x3 mma) with 2-stage
//    cp.async K/V double buffering. CTA = (64-q block, bh), 128 threads.
//    (unchanged from the 1014us-passing round)
// ---------------------------------------------------------------------------
#define QSTR 136                          // bf16 tile stride (272B)
#define FSTAGE_E (2 * 64 * QSTR)          // K+V elems per stage (17408)
#define FSTAGE_B (FSTAGE_E * 2)           // 34816 bytes
#define FLASH_SMEM (2 * FSTAGE_B + 2 * 64 * 4)  // 70144 bytes

__global__ __launch_bounds__(128, 3) void flash_mma(const float* __restrict__ mask,
                                                    float* __restrict__ out) {
    extern __shared__ __align__(16) char smbuf[];
    __nv_bfloat16* KVbase = (__nv_bfloat16*)smbuf;
    float* msk2 = (float*)(smbuf + 2 * FSTAGE_B);   // [2][64]

    const int tid = threadIdx.x, lane = tid & 31, wid = tid >> 5;
    const int bh = blockIdx.y, b = bh >> 4, h = bh & 15;
    const int q0 = blockIdx.x << 6;

    const __nv_bfloat16* __restrict__ Qg = g_QKVc[0] + (size_t)bh * SEQ * 128;
    const __nv_bfloat16* __restrict__ Kg = g_QKVc[1] + (size_t)bh * SEQ * 128;
    const __nv_bfloat16* __restrict__ Vg = g_QKVc[2] + (size_t)bh * SEQ * 128;
    const float* __restrict__ mg = mask + b * SEQ;

    const int ar = (lane & 7) + ((lane & 8) ? 8 : 0);
    const int ac = (lane & 16) ? 8 : 0;
    const int br = (lane & 7) + ((lane >= 16) ? 8 : 0);
    const int bc = (lane & 8) ? 8 : 0;
    const int vr = lane & 15;
    const int vc = (lane >= 16) ? 8 : 0;

    auto issue_kv = [&](int kt, int st) {
        __nv_bfloat16* Kd = KVbase + st * FSTAGE_E;
        __nv_bfloat16* Vd = Kd + 64 * QSTR;
        const __nv_bfloat16* Kt = Kg + (size_t)(kt << 6) * 128;
        const __nv_bfloat16* Vt = Vg + (size_t)(kt << 6) * 128;
#pragma unroll
        for (int v = tid; v < 1024; v += 128) {
            int row = v >> 4, seg = (v & 15) << 3;
            cpa16(Kd + row * QSTR + seg, Kt + row * 128 + seg);
            cpa16(Vd + row * QSTR + seg, Vt + row * 128 + seg);
        }
        if (tid < 16) cpa16(msk2 + st * 64 + tid * 4, mg + (kt << 6) + tid * 4);
    };

    issue_kv(0, 0); CPA_COMMIT();
    {
        __nv_bfloat16* Qstage = KVbase + 1 * FSTAGE_E;
#pragma unroll
        for (int v = tid; v < 1024; v += 128) {
            int row = v >> 4, seg = (v & 15) << 3;
            *(uint4*)(Qstage + row * QSTR + seg) = *(const uint4*)(Qg + (size_t)(q0 + row) * 128 + seg);
        }
    }
    __syncthreads();
    uint32_t Qhi[4][4], Qlo[4][4];
    {
        const __nv_bfloat16* Qstage = KVbase + 1 * FSTAGE_E;
#pragma unroll
        for (int ks = 0; ks < 4; ks++) {
            ldsm4(Qhi[ks][0], Qhi[ks][1], Qhi[ks][2], Qhi[ks][3],
                  smaddr(Qstage + (wid * 16 + ar) * QSTR + ks * 16 + ac));
            ldsm4(Qlo[ks][0], Qlo[ks][1], Qlo[ks][2], Qlo[ks][3],
                  smaddr(Qstage + (wid * 16 + ar) * QSTR + 64 + ks * 16 + ac));
        }
    }
    __syncthreads();

    float O[8][4];
#pragma unroll
    for (int ni = 0; ni < 8; ni++)
#pragma unroll
        for (int q = 0; q < 4; q++) O[ni][q] = 0.f;
    float mr0 = -1e30f, mr1 = -1e30f, lr0 = 0.f, lr1 = 0.f;

    for (int kt = 0; kt < SEQ / 64; kt++) {
        CPA_WAIT0();
        __syncthreads();
        if (kt < SEQ / 64 - 1) { issue_kv(kt + 1, (kt + 1) & 1); CPA_COMMIT(); }

        const __nv_bfloat16* Ks = KVbase + (kt & 1) * FSTAGE_E;
        const __nv_bfloat16* Vs = Ks + 64 * QSTR;
        const float* mskp = msk2 + (kt & 1) * 64;

        float S[8][4];
#pragma unroll
        for (int ni = 0; ni < 8; ni++)
#pragma unroll
            for (int q = 0; q < 4; q++) S[ni][q] = 0.f;

#pragma unroll
        for (int ks = 0; ks < 4; ks++) {          // B = Khi
            uint32_t bf[8][2];
#pragma unroll
            for (int p = 0; p < 4; p++) {
                uint32_t r0, r1, r2, r3;
                ldsm4(r0, r1, r2, r3, smaddr(Ks + (p * 16 + br) * QSTR + ks * 16 + bc));
                bf[2 * p][0] = r0; bf[2 * p][1] = r1; bf[2 * p + 1][0] = r2; bf[2 * p + 1][1] = r3;
            }
#pragma unroll
            for (int ni = 0; ni < 8; ni++) {
                mma16816(S[ni], Qhi[ks], bf[ni]);
                mma16816(S[ni], Qlo[ks], bf[ni]);
            }
        }
#pragma unroll
        for (int ks = 0; ks < 4; ks++) {          // B = Klo, A = Qhi
            uint32_t bf[8][2];
#pragma unroll
            for (int p = 0; p < 4; p++) {
                uint32_t r0, r1, r2, r3;
                ldsm4(r0, r1, r2, r3, smaddr(Ks + (p * 16 + br) * QSTR + 64 + ks * 16 + bc));
                bf[2 * p][0] = r0; bf[2 * p][1] = r1; bf[2 * p + 1][0] = r2; bf[2 * p + 1][1] = r3;
            }
#pragma unroll
            for (int ni = 0; ni < 8; ni++) mma16816(S[ni], Qhi[ks], bf[ni]);
        }

        // ---- online softmax in registers ----
        float mx0 = -1e30f, mx1 = -1e30f;
#pragma unroll
        for (int ni = 0; ni < 8; ni++) {
            float mc0 = mskp[ni * 8 + 2 * (lane & 3)];
            float mc1 = mskp[ni * 8 + 2 * (lane & 3) + 1];
            S[ni][0] += mc0; S[ni][1] += mc1; S[ni][2] += mc0; S[ni][3] += mc1;
            mx0 = fmaxf(mx0, fmaxf(S[ni][0], S[ni][1]));
            mx1 = fmaxf(mx1, fmaxf(S[ni][2], S[ni][3]));
        }
        mx0 = fmaxf(mx0, __shfl_xor_sync(0xffffffffu, mx0, 1));
        mx0 = fmaxf(mx0, __shfl_xor_sync(0xffffffffu, mx0, 2));
        mx1 = fmaxf(mx1, __shfl_xor_sync(0xffffffffu, mx1, 1));
        mx1 = fmaxf(mx1, __shfl_xor_sync(0xffffffffu, mx1, 2));
        float mn0 = fmaxf(mr0, mx0), mn1 = fmaxf(mr1, mx1);
        float scl0 = __expf(mr0 - mn0), scl1 = __expf(mr1 - mn1);
        mr0 = mn0; mr1 = mn1;

        float rs0 = 0.f, rs1 = 0.f;
        uint32_t PhiA[4][4], PloA[4][4];
#pragma unroll
        for (int ni = 0; ni < 8; ni++) {
            float p0 = __expf(S[ni][0] - mn0);
            float p1 = __expf(S[ni][1] - mn0);
            float p2 = __expf(S[ni][2] - mn1);
            float p3 = __expf(S[ni][3] - mn1);
            rs0 += p0 + p1; rs1 += p2 + p3;
            __nv_bfloat162 h01 = __floats2bfloat162_rn(p0, p1);
            __nv_bfloat162 h23 = __floats2bfloat162_rn(p2, p3);
            __nv_bfloat162 l01 = __floats2bfloat162_rn(p0 - __bfloat162float(h01.x),
                                                       p1 - __bfloat162float(h01.y));
            __nv_bfloat162 l23 = __floats2bfloat162_rn(p2 - __bfloat162float(h23.x),
                                                       p3 - __bfloat162float(h23.y));
            int kb = ni >> 1, off = (ni & 1) << 1;
            PhiA[kb][off]     = *(uint32_t*)&h01;
            PhiA[kb][off + 1] = *(uint32_t*)&h23;
            PloA[kb][off]     = *(uint32_t*)&l01;
            PloA[kb][off + 1] = *(uint32_t*)&l23;
        }
        rs0 += __shfl_xor_sync(0xffffffffu, rs0, 1);
        rs0 += __shfl_xor_sync(0xffffffffu, rs0, 2);
        rs1 += __shfl_xor_sync(0xffffffffu, rs1, 1);
        rs1 += __shfl_xor_sync(0xffffffffu, rs1, 2);
        lr0 = lr0 * scl0 + rs0;
        lr1 = lr1 * scl1 + rs1;
#pragma unroll
        for (int ni = 0; ni < 8; ni++) {
            O[ni][0] *= scl0; O[ni][1] *= scl0; O[ni][2] *= scl1; O[ni][3] *= scl1;
        }

        // ---- O += Phi*Vhi + Plo*Vhi + Phi*Vlo ----
#pragma unroll
        for (int ks = 0; ks < 4; ks++) {          // B = Vhi
            uint32_t bf[8][2];
#pragma unroll
            for (int dp = 0; dp < 4; dp++) {
                uint32_t r0, r1, r2, r3;
                ldsm4t(r0, r1, r2, r3, smaddr(Vs + (ks * 16 + vr) * QSTR + dp * 16 + vc));
                bf[2 * dp][0] = r0; bf[2 * dp][1] = r1; bf[2 * dp + 1][0] = r2; bf[2 * dp + 1][1] = r3;
            }
#pragma unroll
            for (int ni = 0; ni < 8; ni++) {
                mma16816(O[ni], PhiA[ks], bf[ni]);
                mma16816(O[ni], PloA[ks], bf[ni]);
            }
        }
#pragma unroll
        for (int ks = 0; ks < 4; ks++) {          // B = Vlo, A = Phi
            uint32_t bf[8][2];
#pragma unroll
            for (int dp = 0; dp < 4; dp++) {
                uint32_t r0, r1, r2, r3;
                ldsm4t(r0, r1, r2, r3, smaddr(Vs + (ks * 16 + vr) * QSTR + 64 + dp * 16 + vc));
                bf[2 * dp][0] = r0; bf[2 * dp][1] = r1; bf[2 * dp + 1][0] = r2; bf[2 * dp + 1][1] = r3;
            }
#pragma unroll
            for (int ni = 0; ni < 8; ni++) mma16816(O[ni], PhiA[ks], bf[ni]);
        }
    }

    // epilogue: normalize, write out[b][s][h*64+d]
    {
        float i0 = 1.f / lr0, i1 = 1.f / lr1;
        int s1 = q0 + wid * 16 + (lane >> 2);
#pragma unroll
        for (int ni = 0; ni < 8; ni++) {
            int d = ni * 8 + 2 * (lane & 3);
            float2 v0 = make_float2(O[ni][0] * i0, O[ni][1] * i0);
            float2 v1 = make_float2(O[ni][2] * i1, O[ni][3] * i1);
            *(float2*)(out + ((size_t)(b * SEQ + s1) * HID) + h * 64 + d)     = v0;
            *(float2*)(out + ((size_t)(b * SEQ + s1 + 8) * HID) + h * 64 + d) = v1;
        }
    }
}

// ---------------------------------------------------------------------------
// Launch
// ---------------------------------------------------------------------------
extern "C" void kernel_launch(void* const* d_in, const int* in_sizes, int n_in,
                              void* d_out, int out_size) {
    (void)in_sizes; (void)n_in; (void)out_size;
    const float* x    = (const float*)d_in[0];
    const float* mask = (const float*)d_in[1];
    Ptrs3 W  = {{(const float*)d_in[2], (const float*)d_in[6],  (const float*)d_in[10]}};
    Ptrs3 bi = {{(const float*)d_in[3], (const float*)d_in[7],  (const float*)d_in[11]}};
    Ptrs3 A  = {{(const float*)d_in[4], (const float*)d_in[8],  (const float*)d_in[12]}};
    Ptrs3 Bl = {{(const float*)d_in[5], (const float*)d_in[9],  (const float*)d_in[13]}};
    float* out = (float*)d_out;

    fold_split_w<<<dim3((HID * HID) / 256, 3), 256>>>(W, A, Bl);
    split_x<<<(M_TOT * HID / 4) / 256, 256>>>(x);

    cudaFuncSetAttribute(qkv_gemm_mma, cudaFuncAttributeMaxDynamicSharedMemorySize, GEMM_SMEM);
    qkv_gemm_mma<<<dim3(HID / 128, M_TOT / 128, 3), 256, GEMM_SMEM>>>(bi);

    cudaFuncSetAttribute(flash_mma, cudaFuncAttributeMaxDynamicSharedMemorySize, FLASH_SMEM);
    flash_mma<<<dim3(SEQ / 64, NBH), 128, FLASH_SMEM>>>(mask, out);
}